// round 7
// baseline (speedup 1.0000x reference)
#include <cuda_runtime.h>
#include <cuda_bf16.h>
#include <math.h>
#include <stdint.h>

#define NN 4000
#define BB 4
#define FF 16
#define TT 16
#define OO 16

__device__ float g_u2u3[NN];
__device__ float g_tlhs[BB*TT];
__device__ float g_trhs[BB*TT];
__device__ float g_E[BB*TT*TT];
__device__ float g_xTAt[BB*NN*FF*TT];
__device__ float g_slhs[BB*NN*FF];
__device__ float g_srhs[BB*NN*FF];
__device__ __align__(256) int8_t g_va1[(size_t)NN*NN];          // (Vs-0.5) hi digit
__device__ __align__(256) int8_t g_va2[(size_t)NN*NN];          // lo digit
__device__ __align__(256) int8_t g_pb1[(size_t)BB*NN*NN];       // (sig-0.5)^T hi digit [b][k][m]
__device__ __align__(256) int8_t g_pb2[(size_t)BB*NN*NN];       // lo digit
__device__ float g_colsum[BB*NN];                               // sum_m (sig-0.5)[m,k]
__device__ __align__(256) __nv_bfloat16 g_spT_h[(size_t)BB*NN*NN]; // softmaxed S split (A of xSAtt)
__device__ __align__(256) __nv_bfloat16 g_spT_l[(size_t)BB*NN*NN];
__device__ __align__(256) __nv_bfloat16 g_lap_h[(size_t)NN*NN];
__device__ __align__(256) __nv_bfloat16 g_lap_l[(size_t)NN*NN];
__device__ __align__(256) __nv_bfloat16 g_bT_h[(size_t)BB*256*NN];  // transposed B panels
__device__ __align__(256) __nv_bfloat16 g_bT_l[(size_t)BB*256*NN];
__device__ __align__(256) float g_S[(size_t)BB*NN*NN];
__device__ float g_Tx0[BB*NN*FF*TT];
__device__ float g_Tx1[BB*NN*FF*TT];
__device__ float g_Tx2[BB*NN*FF*TT];
__device__ float g_y[BB*NN*OO];
__device__ float g_stats[BB*2];

__device__ __forceinline__ float sigmoidf_(float v){ return 1.f/(1.f+__expf(-v)); }

// ---- ptx helpers (sm_80-generic) ----
__device__ __forceinline__ uint32_t smem_u32(const void* p){
    uint32_t a;
    asm("{ .reg .u64 t; cvta.to.shared.u64 t, %1; cvt.u32.u64 %0, t; }" : "=r"(a) : "l"(p));
    return a;
}
#define SWZ(o)   ((uint32_t)(o) ^ ((((uint32_t)(o)) >> 3) & 0x70u))
#define SWZ64(o) ((uint32_t)(o) ^ ((((uint32_t)(o)) >> 3) & 0x30u))
__device__ __forceinline__ void cpa16(uint32_t dst, const void* src, bool p){
    int sz = p ? 16 : 0;
    asm volatile("cp.async.cg.shared.global [%0], [%1], 16, %2;" :: "r"(dst), "l"(src), "r"(sz) : "memory");
}
__device__ __forceinline__ void cpa_commit(){ asm volatile("cp.async.commit_group;" ::: "memory"); }
__device__ __forceinline__ void ldsm4(uint32_t* r, uint32_t addr){
    asm volatile("ldmatrix.sync.aligned.m8n8.x4.shared.b16 {%0,%1,%2,%3}, [%4];"
        : "=r"(r[0]),"=r"(r[1]),"=r"(r[2]),"=r"(r[3]) : "r"(addr));
}
__device__ __forceinline__ void ldsm2(uint32_t* r, uint32_t addr){
    asm volatile("ldmatrix.sync.aligned.m8n8.x2.shared.b16 {%0,%1}, [%2];"
        : "=r"(r[0]),"=r"(r[1]) : "r"(addr));
}
__device__ __forceinline__ void mma16816(float* c, const uint32_t* a, const uint32_t* b){
    asm volatile("mma.sync.aligned.m16n8k16.row.col.f32.bf16.bf16.f32 "
        "{%0,%1,%2,%3}, {%4,%5,%6,%7}, {%8,%9}, {%0,%1,%2,%3};"
        : "+f"(c[0]),"+f"(c[1]),"+f"(c[2]),"+f"(c[3])
        : "r"(a[0]),"r"(a[1]),"r"(a[2]),"r"(a[3]), "r"(b[0]),"r"(b[1]));
}
__device__ __forceinline__ void mma_s8(int* c, const uint32_t* a, const uint32_t* b){
    asm volatile("mma.sync.aligned.m16n8k32.row.col.s32.s8.s8.s32 "
        "{%0,%1,%2,%3}, {%4,%5,%6,%7}, {%8,%9}, {%0,%1,%2,%3};"
        : "+r"(c[0]),"+r"(c[1]),"+r"(c[2]),"+r"(c[3])
        : "r"(a[0]),"r"(a[1]),"r"(a[2]),"r"(a[3]), "r"(b[0]),"r"(b[1]));
}

// ---- small kernels ----
__global__ void k_u2u3(const float* __restrict__ U2, const float* __restrict__ U3){
    int n = blockIdx.x*blockDim.x + threadIdx.x;
    if (n < NN){
        float s = 0.f;
        #pragma unroll
        for (int g=0; g<FF; g++) s += U2[g*NN+n]*U3[g];
        g_u2u3[n] = s;
    }
}
__global__ void k_tred(const float* __restrict__ x, const float* __restrict__ U1){
    int b = blockIdx.x >> 4, t = blockIdx.x & 15;
    int tid = threadIdx.x;
    float s1 = 0.f, s2 = 0.f;
    for (int i = tid; i < NN*FF; i += 256){
        int n = i >> 4, f = i & 15;
        float v = x[((size_t)(b*NN+n)*FF+f)*TT + t];
        s1 += v*U1[n]; s2 += v*g_u2u3[n];
    }
    __shared__ float r1[256], r2[256];
    r1[tid]=s1; r2[tid]=s2; __syncthreads();
    for (int o=128; o>0; o>>=1){
        if (tid<o){ r1[tid]+=r1[tid+o]; r2[tid]+=r2[tid+o]; }
        __syncthreads();
    }
    if (tid==0){ g_tlhs[b*TT+t]=r1[0]; g_trhs[b*TT+t]=r2[0]; }
}
__global__ void k_E(const float* __restrict__ Ve, const float* __restrict__ be){
    __shared__ float tl[BB*TT], tr[BB*TT], sVe[TT*TT], sbe[TT*TT], Eb[BB*TT*TT];
    int tid = threadIdx.x;
    if (tid < BB*TT){ tl[tid]=g_tlhs[tid]; tr[tid]=g_trhs[tid]; }
    if (tid < TT*TT){ sVe[tid]=Ve[tid]; sbe[tid]=be[tid]; }
    __syncthreads();
    for (int idx = tid; idx < BB*TT*TT; idx += 256){
        int b = idx>>8, t = (idx>>4)&15, r = idx&15;
        float s = 0.f;
        #pragma unroll
        for (int ss=0; ss<TT; ss++)
            s += sVe[t*TT+ss]*(1.f/(1.f+expf(-(tl[b*TT+ss]*tr[b*TT+r] + sbe[ss*TT+r]))));
        Eb[idx] = s;
    }
    __syncthreads();
    if (tid < BB*TT){
        int base = tid*TT;
        float m = -1e30f;
        for (int r=0;r<TT;r++) m = fmaxf(m, Eb[base+r]);
        float e[TT]; float sum = 0.f;
        for (int r=0;r<TT;r++){ e[r]=expf(Eb[base+r]-m); sum+=e[r]; }
        float inv = 1.f/sum;
        for (int r=0;r<TT;r++) g_E[base+r] = e[r]*inv;
    }
}
__global__ void k_xTAt(const float* __restrict__ x, const float* __restrict__ W1,
                       const float* __restrict__ W2, const float* __restrict__ W3){
    int bn = blockIdx.x;
    int b = bn / NN;
    int tid = threadIdx.x;
    __shared__ float xs[256], Es[256], sr0[16];
    xs[tid] = x[(size_t)bn*256 + tid];
    Es[tid] = g_E[b*256 + tid];
    __syncthreads();
    int f = tid >> 4, t = tid & 15;
    float s = 0.f;
    #pragma unroll
    for (int ss=0; ss<TT; ss++) s += Es[t*16+ss]*xs[f*16+ss];
    g_xTAt[(size_t)bn*256 + tid] = s;
    if (tid < 16){
        float a=0.f, c=0.f;
        #pragma unroll
        for (int t2=0;t2<16;t2++){ float v = xs[tid*16+t2]; a += v*W1[t2]; c += v*W3[t2]; }
        g_slhs[bn*16+tid] = a;
        sr0[tid] = c;
    }
    __syncthreads();
    if (tid < 16){
        float g = 0.f;
        #pragma unroll
        for (int kk=0;kk<16;kk++) g += W2[tid*16+kk]*sr0[kk];
        g_srhs[bn*16+tid] = g;
    }
}
// quantize (Vs-0.5) -> two int8 digits, combined scale 32512 = 254*128
__global__ void k_vs_q(const float* __restrict__ Vs){
    size_t i = (size_t)blockIdx.x*256 + threadIdx.x;
    if (i < (size_t)NN*NN){
        float s = Vs[i] - 0.5f;
        int d1 = __float2int_rn(s*254.f);
        d1 = max(-127, min(127, d1));
        float r = s - (float)d1*(1.f/254.f);
        int d2 = __float2int_rn(r*32512.f);
        d2 = max(-127, min(127, d2));
        g_va1[i] = (int8_t)d1;
        g_va2[i] = (int8_t)d2;
    }
}
__global__ void k_lap_split(const float* __restrict__ lap){
    size_t i = (size_t)blockIdx.x*256 + threadIdx.x;
    if (i < (size_t)NN*NN){
        float v = lap[i];
        __nv_bfloat16 h = __float2bfloat16(v);
        g_lap_h[i] = h;
        g_lap_l[i] = __float2bfloat16(v - __bfloat162float(h));
    }
}
__global__ void k_zero_cs(){
    int i = blockIdx.x*256 + threadIdx.x;
    if (i < BB*NN) g_colsum[i] = 0.f;
}
// transpose-split: X [b][NN][256] fp32 -> XT [b][256][NN] bf16 h/l
__global__ void k_tsplit(const float* __restrict__ X){
    int b = blockIdx.z;
    int m0 = blockIdx.x*32, c0 = blockIdx.y*32;
    int tx = threadIdx.x & 31, ty = threadIdx.x >> 5;
    __shared__ float t[32][33];
    const float* Xb = X + (size_t)b*NN*256;
    #pragma unroll
    for (int i=0;i<4;i++){
        int row = ty + i*8;
        t[row][tx] = Xb[(size_t)(m0+row)*256 + c0 + tx];
    }
    __syncthreads();
    __nv_bfloat16* Th = g_bT_h + (size_t)b*256*NN;
    __nv_bfloat16* Tl = g_bT_l + (size_t)b*256*NN;
    #pragma unroll
    for (int i=0;i<4;i++){
        int row = ty + i*8;
        float v = t[tx][row];
        __nv_bfloat16 h = __float2bfloat16(v);
        size_t o = (size_t)(c0+row)*NN + m0 + tx;
        Th[o] = h;
        Tl[o] = __float2bfloat16(v - __bfloat162float(h));
    }
}
// sigmoid(prod+bs) - 0.5, transposed [b][k][m], int8 2-digit quant + colsum
__global__ void k_sigP(const float* __restrict__ bs){
    int b = blockIdx.z;
    int m0 = blockIdx.y*32, k0 = blockIdx.x*32;
    int tid = threadIdx.x, lane = tid&31;
    __shared__ float Lm[32][17], Rk[32][17], sbs[32][33];
    for (int i = tid; i < 512; i += 256){
        int r = i>>4, c = i&15;
        Lm[r][c] = g_slhs[(b*NN + m0 + r)*16 + c];
        Rk[r][c] = g_srhs[(b*NN + k0 + r)*16 + c];
    }
    for (int i = tid; i < 1024; i += 256){
        int mi = i>>5, ki = i&31;
        sbs[mi][ki] = bs[(size_t)(m0+mi)*NN + k0 + ki];
    }
    __syncthreads();
    for (int e = tid; e < 1024; e += 256){
        int ki = e>>5, mi = e&31;   // mi == lane
        float d = sbs[mi][ki];
        #pragma unroll
        for (int f=0; f<16; f++) d += Lm[mi][f]*Rk[ki][f];
        float s = sigmoidf_(d) - 0.5f;
        int d1 = __float2int_rn(s*254.f);
        d1 = max(-127, min(127, d1));
        float r = s - (float)d1*(1.f/254.f);
        int d2 = __float2int_rn(r*32512.f);
        d2 = max(-127, min(127, d2));
        size_t o = (size_t)b*NN*NN + (size_t)(k0+ki)*NN + (m0+mi);
        g_pb1[o] = (int8_t)d1;
        g_pb2[o] = (int8_t)d2;
        // colsum over mi (warp lanes) for this ki
        float cs = s;
        #pragma unroll
        for (int off=16; off>0; off>>=1) cs += __shfl_down_sync(0xFFFFFFFFu, cs, off);
        if (lane==0) atomicAdd(&g_colsum[b*NN + k0 + ki], cs);
    }
}

// ---- int8 2-digit tensor GEMM: S[b,n,k] = sum_m (Vs-0.5)(sig-0.5) + 0.5*colsum[k] ----
#define KCHUNK 64
#define NCHUNK 63
#define I8_STG 32768
#define I8_NSTAGE 3
#define I8_SMEM (I8_NSTAGE*I8_STG + 1024)

__global__ void __launch_bounds__(256,1) gemm_S_i8(){
    extern __shared__ char dsm[];
    uint32_t sb = (smem_u32(dsm) + 1023u) & ~1023u;
    int tid = threadIdx.x, lane = tid&31, wid = tid>>5;
    int b = blockIdx.z;
    int mBase = blockIdx.y*128, nBase = blockIdx.x*128;
    int wm = wid>>1, wn = wid&1;

    const int8_t* A1 = g_va1;
    const int8_t* A2 = g_va2;
    const int8_t* B1 = g_pb1 + (size_t)b*NN*NN;
    const int8_t* B2 = g_pb2 + (size_t)b*NN*NN;

    int acc11[2][8][4], acc12[2][8][4];
    #pragma unroll
    for (int i=0;i<2;i++)
        #pragma unroll
        for (int j=0;j<8;j++)
            #pragma unroll
            for (int q=0;q<4;q++){ acc11[i][j][q]=0; acc12[i][j][q]=0; }

    #define ISSUE_I8(c_) do{ \
        int st_ = (c_)%I8_NSTAGE; uint32_t stg_ = sb + st_*I8_STG; \
        int k0_ = (c_)*KCHUNK; \
        _Pragma("unroll") \
        for (int j_=0;j_<8;j_++){ \
            int op_ = j_*256+tid; int plane_ = op_>>9; int row_ = (op_>>2)&127; int seg_ = op_&3; \
            int kk_ = k0_ + seg_*16; \
            uint32_t dst_ = stg_ + plane_*8192 + SWZ64(row_*64 + seg_*16); \
            const int8_t* src_; bool v_; \
            if (plane_ < 2){ \
                v_ = (kk_ < NN) && ((mBase+row_) < NN); \
                src_ = (plane_ ? A2 : A1) + (size_t)(mBase+row_)*NN + kk_; \
            } else { \
                v_ = (kk_ < NN) && ((nBase+row_) < NN); \
                src_ = (plane_==2 ? B1 : B2) + (size_t)(nBase+row_)*NN + kk_; \
            } \
            cpa16(dst_, src_, v_); \
        } \
        cpa_commit(); \
    }while(0)

    ISSUE_I8(0);
    ISSUE_I8(1);
    ISSUE_I8(2);

    for (int c=0;c<NCHUNK;c++){
        asm volatile("cp.async.wait_group 2;" ::: "memory");
        __syncthreads();
        uint32_t stg = sb + (c%I8_NSTAGE)*I8_STG;
        #pragma unroll
        for (int ks=0;ks<2;ks++){          // two k32 steps per 64-chunk
            uint32_t a1f[2][4], a2f[2][4];
            #pragma unroll
            for (int mt=0;mt<2;mt++){
                int row = wm*32 + mt*16 + (lane&15);
                uint32_t bo = SWZ64(row*64 + ks*32 + (lane>>4)*16);
                ldsm4(a1f[mt], stg + 0    + bo);
                ldsm4(a2f[mt], stg + 8192 + bo);
            }
            uint32_t b1f[8][2], b2f[8][2];
            #pragma unroll
            for (int nt=0;nt<8;nt++){
                int row = wn*64 + nt*8 + (lane&7);
                uint32_t bo = SWZ64(row*64 + ks*32 + ((lane>>3)&1)*16);
                ldsm2(b1f[nt], stg + 16384 + bo);
                ldsm2(b2f[nt], stg + 24576 + bo);
            }
            #pragma unroll
            for (int mt=0;mt<2;mt++)
                #pragma unroll
                for (int nt=0;nt<8;nt++){
                    mma_s8(acc11[mt][nt], a1f[mt], b1f[nt]);
                    mma_s8(acc12[mt][nt], a1f[mt], b2f[nt]);
                    mma_s8(acc12[mt][nt], a2f[mt], b1f[nt]);
                }
        }
        __syncthreads();
        if (c+I8_NSTAGE < NCHUNK){ ISSUE_I8(c+I8_NSTAGE); }
        else { cpa_commit(); }
    }
    #undef ISSUE_I8

    const float INVSS = (float)(1.0/1057030144.0);   // 1/32512^2
    float* C = g_S + (size_t)b*NN*NN;
    const float* CS = g_colsum + b*NN;
    int tig = lane&3, grp = lane>>2;
    #pragma unroll
    for (int mt=0;mt<2;mt++){
        int r0 = mBase + wm*32 + mt*16 + grp;
        int r1 = r0 + 8;
        #pragma unroll
        for (int nt=0;nt<8;nt++){
            int c0 = nBase + wn*64 + nt*8 + tig*2;
            if (c0 < NN){
                bool c1ok = (c0+1) < NN;
                float cs0 = 0.5f*CS[c0];
                float cs1 = c1ok ? 0.5f*CS[c0+1] : 0.f;
                if (r0 < NN){
                    C[(size_t)r0*NN + c0] =
                        (float)(16384LL*(long long)acc11[mt][nt][0] + 128LL*(long long)acc12[mt][nt][0])*INVSS + cs0;
                    if (c1ok)
                        C[(size_t)r0*NN + c0 + 1] =
                        (float)(16384LL*(long long)acc11[mt][nt][1] + 128LL*(long long)acc12[mt][nt][1])*INVSS + cs1;
                }
                if (r1 < NN){
                    C[(size_t)r1*NN + c0] =
                        (float)(16384LL*(long long)acc11[mt][nt][2] + 128LL*(long long)acc12[mt][nt][2])*INVSS + cs0;
                    if (c1ok)
                        C[(size_t)r1*NN + c0 + 1] =
                        (float)(16384LL*(long long)acc11[mt][nt][3] + 128LL*(long long)acc12[mt][nt][3])*INVSS + cs1;
                }
            }
        }
    }
}

// ---- generic bf16-split tensor GEMM (3-pass), for the small GEMMs ----
#define NSTAGE 3
#define STG_BYTES 65536
#define OFF_AH 0
#define OFF_AL 16384
#define OFF_BH 32768
#define OFF_BL 49152
#define SMEM_REQ (NSTAGE*STG_BYTES + 1024)

__global__ void __launch_bounds__(256,1) gemm_bsplit(
    const __nv_bfloat16* __restrict__ gAh, const __nv_bfloat16* __restrict__ gAl, long long sAb,
    const __nv_bfloat16* __restrict__ gBh, const __nv_bfloat16* __restrict__ gBl, long long sBb,
    float* __restrict__ gC, const float* __restrict__ gD, long long sCb,
    int ldc, int Ncols, float alpha, float beta)
{
    extern __shared__ char dsm[];
    uint32_t sb = (smem_u32(dsm) + 1023u) & ~1023u;
    int tid = threadIdx.x, lane = tid&31, wid = tid>>5;
    int b = blockIdx.z;
    int mBase = blockIdx.y*128, nBase = blockIdx.x*128;
    int wm = wid>>1, wn = wid&1;

    const __nv_bfloat16* Ahp = gAh + (size_t)b*sAb;
    const __nv_bfloat16* Alp = gAl + (size_t)b*sAb;
    const __nv_bfloat16* Bhp = gBh + (size_t)b*sBb;
    const __nv_bfloat16* Blp = gBl + (size_t)b*sBb;

    float acc[2][8][4];
    #pragma unroll
    for (int i=0;i<2;i++)
        #pragma unroll
        for (int j=0;j<8;j++)
            #pragma unroll
            for (int q=0;q<4;q++) acc[i][j][q]=0.f;

    #define ISSUE_STAGE(c_) do{ \
        int st_ = (c_)%NSTAGE; uint32_t stg_ = sb + st_*STG_BYTES; \
        int k0_ = (c_)*KCHUNK; \
        _Pragma("unroll") \
        for (int j_=0;j_<4;j_++){ \
            int op_ = j_*256+tid; int row_ = op_>>3, ch_ = op_&7; \
            int kk_ = k0_ + ch_*8; \
            uint32_t so_ = SWZ(row_*128 + ch_*16); \
            bool va_ = (kk_ < NN) && ((mBase+row_) < NN); \
            size_t ga_ = va_ ? ((size_t)(mBase+row_)*NN + kk_) : 0; \
            cpa16(stg_+OFF_AH+so_, Ahp+ga_, va_); \
            cpa16(stg_+OFF_AL+so_, Alp+ga_, va_); \
            bool vb_ = (kk_ < NN) && ((nBase+row_) < Ncols); \
            size_t gb_ = vb_ ? ((size_t)(nBase+row_)*NN + kk_) : 0; \
            cpa16(stg_+OFF_BH+so_, Bhp+gb_, vb_); \
            cpa16(stg_+OFF_BL+so_, Blp+gb_, vb_); \
        } \
        cpa_commit(); \
    }while(0)

    ISSUE_STAGE(0);
    ISSUE_STAGE(1);
    ISSUE_STAGE(2);

    for (int c=0;c<NCHUNK;c++){
        asm volatile("cp.async.wait_group 2;" ::: "memory");
        __syncthreads();
        uint32_t stg = sb + (c%NSTAGE)*STG_BYTES;
        #pragma unroll
        for (int ks=0;ks<4;ks++){
            uint32_t ah[2][4], al[2][4];
            #pragma unroll
            for (int mt=0;mt<2;mt++){
                int row = wm*32 + mt*16 + (lane&15);
                uint32_t bo = SWZ(row*128 + ks*32 + (lane>>4)*16);
                ldsm4(ah[mt], stg+OFF_AH+bo);
                ldsm4(al[mt], stg+OFF_AL+bo);
            }
            uint32_t bh[8][2], bl[8][2];
            #pragma unroll
            for (int nt=0;nt<8;nt++){
                int row = wn*64 + nt*8 + (lane&7);
                uint32_t bo = SWZ(row*128 + ks*32 + ((lane>>3)&1)*16);
                ldsm2(bh[nt], stg+OFF_BH+bo);
                ldsm2(bl[nt], stg+OFF_BL+bo);
            }
            #pragma unroll
            for (int mt=0;mt<2;mt++)
                #pragma unroll
                for (int nt=0;nt<8;nt++){
                    mma16816(acc[mt][nt], ah[mt], bh[nt]);
                    mma16816(acc[mt][nt], ah[mt], bl[nt]);
                    mma16816(acc[mt][nt], al[mt], bh[nt]);
                }
        }
        __syncthreads();
        if (c+NSTAGE < NCHUNK){ ISSUE_STAGE(c+NSTAGE); }
        else { cpa_commit(); }
    }
    #undef ISSUE_STAGE

    float* C = gC + (size_t)b*sCb;
    const float* D = gD ? gD + (size_t)b*sCb : (const float*)0;
    int tig = lane&3, grp = lane>>2;
    #pragma unroll
    for (int mt=0;mt<2;mt++){
        int r0 = mBase + wm*32 + mt*16 + grp;
        int r1 = r0 + 8;
        #pragma unroll
        for (int nt=0;nt<8;nt++){
            int c0 = nBase + wn*64 + nt*8 + tig*2;
            if (c0 < Ncols){
                bool c1ok = (c0+1) < Ncols;
                if (r0 < NN){
                    float v0 = alpha*acc[mt][nt][0];
                    if (D) v0 += beta*D[(size_t)r0*ldc + c0];
                    C[(size_t)r0*ldc + c0] = v0;
                    if (c1ok){
                        float v1 = alpha*acc[mt][nt][1];
                        if (D) v1 += beta*D[(size_t)r0*ldc + c0 + 1];
                        C[(size_t)r0*ldc + c0 + 1] = v1;
                    }
                }
                if (r1 < NN){
                    float v2 = alpha*acc[mt][nt][2];
                    if (D) v2 += beta*D[(size_t)r1*ldc + c0];
                    C[(size_t)r1*ldc + c0] = v2;
                    if (c1ok){
                        float v3 = alpha*acc[mt][nt][3];
                        if (D) v3 += beta*D[(size_t)r1*ldc + c0 + 1];
                        C[(size_t)r1*ldc + c0 + 1] = v3;
                    }
                }
            }
        }
    }
}

// softmax over last dim of S; writes bf16 h/l split (A operand of xSAtt)
__global__ void k_softmax(){
    __shared__ float row[NN];
    __shared__ float red[256];
    int tid = threadIdx.x;
    size_t base = (size_t)blockIdx.x * NN;
    float m = -1e30f;
    for (int i = tid; i < NN; i += 256){ float v = g_S[base+i]; row[i]=v; m = fmaxf(m,v); }
    red[tid]=m; __syncthreads();
    for (int o=128;o>0;o>>=1){ if (tid<o) red[tid]=fmaxf(red[tid],red[tid+o]); __syncthreads(); }
    m = red[0]; __syncthreads();
    float s = 0.f;
    for (int i = tid; i < NN; i += 256){ float e = __expf(row[i]-m); row[i]=e; s += e; }
    red[tid]=s; __syncthreads();
    for (int o=128;o>0;o>>=1){ if (tid<o) red[tid]+=red[tid+o]; __syncthreads(); }
    float inv = 1.f/red[0];
    for (int i = tid; i < NN; i += 256){
        float p = row[i]*inv;
        __nv_bfloat16 h = __float2bfloat16(p);
        g_spT_h[base+i] = h;
        g_spT_l[base+i] = __float2bfloat16(p - __bfloat162float(h));
    }
}

__global__ void k_final(const float* __restrict__ x, const float* __restrict__ cheb,
                        const float* __restrict__ tw, const float* __restrict__ tb){
    int bn = blockIdx.x;
    int tid = threadIdx.x;
    __shared__ float xs[256], t0[256], t1[256], t2[256], ts0[16], ts1[16], ts2[16];
    size_t rb = (size_t)bn*256;
    xs[tid]=x[rb+tid]; t0[tid]=g_Tx0[rb+tid]; t1[tid]=g_Tx1[rb+tid]; t2[tid]=g_Tx2[rb+tid];
    __syncthreads();
    if (tid < 48){
        int kk = tid>>4, f = tid&15;
        const float* src = (kk==0) ? t0 : ((kk==1) ? t1 : t2);
        float s = 0.f;
        #pragma unroll
        for (int t=0;t<16;t++) s += src[f*16+t];
        float* dst = (kk==0) ? ts0 : ((kk==1) ? ts1 : ts2);
        dst[f] = s;
    }
    __syncthreads();
    if (tid < 16){
        int o = tid;
        float tm = 0.f;
        #pragma unroll
        for (int c=0;c<16;c++)
            #pragma unroll
            for (int t=0;t<16;t++) tm += xs[c*16+t]*tw[(o*16+c)*16+t];
        float sp = 0.f;
        #pragma unroll
        for (int f=0;f<16;f++)
            sp += ts0[f]*cheb[f*16+o] + ts1[f]*cheb[256+f*16+o] + ts2[f]*cheb[512+f*16+o];
        g_y[bn*16+o] = sp*(1.f/16.f) + tm + tb[o] + xs[o*16+15];
    }
}

__global__ void k_stats(){
    int b = blockIdx.x, tid = threadIdx.x;
    double s = 0.0, ss = 0.0;
    for (int i = tid; i < NN*OO; i += 256){
        float v = g_y[b*NN*OO + i];
        s += (double)v; ss += (double)v*(double)v;
    }
    __shared__ double rs[256], rq[256];
    rs[tid]=s; rq[tid]=ss; __syncthreads();
    for (int o=128;o>0;o>>=1){ if (tid<o){ rs[tid]+=rs[tid+o]; rq[tid]+=rq[tid+o]; } __syncthreads(); }
    if (tid==0){
        double mean = rs[0]/(double)(NN*OO);
        double var  = rq[0]/(double)(NN*OO) - mean*mean;
        g_stats[b*2]   = (float)mean;
        g_stats[b*2+1] = (float)(1.0/sqrt(var + 1e-5));
    }
}
__global__ void k_out(const float* __restrict__ lng, const float* __restrict__ lnb,
                      float* __restrict__ out){
    int i = blockIdx.x*256 + threadIdx.x;
    if (i < BB*NN*OO){
        int b  = i / (NN*OO);
        int no = i % (NN*OO);
        float v = (g_y[i]-g_stats[b*2])*g_stats[b*2+1]*lng[no] + lnb[no];
        out[i] = fmaxf(v, 0.f);
    }
}

extern "C" void kernel_launch(void* const* d_in, const int* in_sizes, int n_in,
                              void* d_out, int out_size){
    const float* x    = (const float*)d_in[0];
    const float* lap  = (const float*)d_in[1];
    const float* W1   = (const float*)d_in[2];
    const float* W2   = (const float*)d_in[3];
    const float* W3   = (const float*)d_in[4];
    const float* bs   = (const float*)d_in[5];
    const float* Vs   = (const float*)d_in[6];
    const float* U1   = (const float*)d_in[7];
    const float* U2   = (const float*)d_in[8];
    const float* U3   = (const float*)d_in[9];
    const float* be   = (const float*)d_in[10];
    const float* Ve   = (const float*)d_in[11];
    const float* cheb = (const float*)d_in[12];
    const float* tw   = (const float*)d_in[13];
    const float* tb   = (const float*)d_in[14];
    const float* lng  = (const float*)d_in[15];
    const float* lnb  = (const float*)d_in[16];
    float* out = (float*)d_out;

    static int smem_set = 0;
    if (!smem_set){
        cudaFuncSetAttribute(gemm_bsplit, cudaFuncAttributeMaxDynamicSharedMemorySize, SMEM_REQ);
        cudaFuncSetAttribute(gemm_S_i8,   cudaFuncAttributeMaxDynamicSharedMemorySize, I8_SMEM);
        smem_set = 1;
    }

    float *g_T0p, *g_T1p, *g_xTp;
    __nv_bfloat16 *spT_h_p, *spT_l_p, *lap_h_p, *lap_l_p, *bT_h_p, *bT_l_p;
    cudaGetSymbolAddress((void**)&g_T0p, g_Tx0);
    cudaGetSymbolAddress((void**)&g_T1p, g_Tx1);
    cudaGetSymbolAddress((void**)&g_xTp, g_xTAt);
    cudaGetSymbolAddress((void**)&spT_h_p, g_spT_h);
    cudaGetSymbolAddress((void**)&spT_l_p, g_spT_l);
    cudaGetSymbolAddress((void**)&lap_h_p, g_lap_h);
    cudaGetSymbolAddress((void**)&lap_l_p, g_lap_l);
    cudaGetSymbolAddress((void**)&bT_h_p,  g_bT_h);
    cudaGetSymbolAddress((void**)&bT_l_p,  g_bT_l);
    float *g_T2p;
    cudaGetSymbolAddress((void**)&g_T2p, g_Tx2);

    k_u2u3<<<(NN+255)/256, 256>>>(U2, U3);
    k_tred<<<BB*TT, 256>>>(x, U1);
    k_E<<<1, 256>>>(Ve, be);
    k_xTAt<<<BB*NN, 256>>>(x, W1, W2, W3);
    k_vs_q<<<(NN*NN+255)/256, 256>>>(Vs);
    k_lap_split<<<(NN*NN+255)/256, 256>>>(lap);
    k_zero_cs<<<(BB*NN+255)/256, 256>>>();
    k_sigP<<<dim3(125,125,BB), 256>>>(bs);

    // S = (Vs-0.5) @ (sig-0.5) + 0.5*colsum   (int8 2-digit, m16n8k32)
    gemm_S_i8<<<dim3(32,32,BB), 256, I8_SMEM>>>();

    k_softmax<<<BB*NN, 256>>>();
    k_tsplit<<<dim3(125,8,BB), 256>>>(g_xTp);

    gemm_bsplit<<<dim3(2,32,BB), 256, SMEM_REQ>>>(
        spT_h_p, spT_l_p, (long long)NN*NN, bT_h_p, bT_l_p, (long long)256*NN,
        g_T0p, (const float*)0, (long long)NN*256, 256, 256, 1.f, 0.f);

    k_tsplit<<<dim3(125,8,BB), 256>>>(g_T0p);

    gemm_bsplit<<<dim3(2,32,BB), 256, SMEM_REQ>>>(
        lap_h_p, lap_l_p, 0LL, bT_h_p, bT_l_p, (long long)256*NN,
        g_T1p, (const float*)0, (long long)NN*256, 256, 256, 1.f, 0.f);

    k_tsplit<<<dim3(125,8,BB), 256>>>(g_T1p);

    gemm_bsplit<<<dim3(2,32,BB), 256, SMEM_REQ>>>(
        lap_h_p, lap_l_p, 0LL, bT_h_p, bT_l_p, (long long)256*NN,
        g_T2p, g_T0p, (long long)NN*256, 256, 256, 2.f, -1.f);

    k_final<<<BB*NN, 256>>>(x, cheb, tw, tb);
    k_stats<<<BB, 256>>>();
    k_out<<<(BB*NN*OO+255)/256, 256>>>(lng, lnb, out);
}

// round 9
// speedup vs baseline: 2.2625x; 2.2625x over previous
#include <cuda_runtime.h>
#include <cuda_bf16.h>
#include <math.h>
#include <stdint.h>

#define NN 4000
#define BB 4
#define FF 16
#define TT 16
#define OO 16

__device__ float g_u2u3[NN];
__device__ float g_tlhs[BB*TT];
__device__ float g_trhs[BB*TT];
__device__ float g_E[BB*TT*TT];
__device__ float g_xTAt[BB*NN*FF*TT];
__device__ float g_slhs[BB*NN*FF];
__device__ float g_srhs[BB*NN*FF];
__device__ __align__(256) __nv_bfloat16 g_vs_h[(size_t)NN*NN];
__device__ __align__(256) __nv_bfloat16 g_vs_l[(size_t)NN*NN];
__device__ __align__(256) __nv_bfloat16 g_spT_h[(size_t)BB*NN*NN]; // sigP^T pre-gemm; softmaxed S post
__device__ __align__(256) __nv_bfloat16 g_spT_l[(size_t)BB*NN*NN];
__device__ __align__(256) __nv_bfloat16 g_lap_h[(size_t)NN*NN];
__device__ __align__(256) __nv_bfloat16 g_lap_l[(size_t)NN*NN];
__device__ __align__(256) __nv_bfloat16 g_bT_h[(size_t)BB*256*NN];  // transposed B panels
__device__ __align__(256) __nv_bfloat16 g_bT_l[(size_t)BB*256*NN];
__device__ __align__(256) float g_S[(size_t)BB*NN*NN];
__device__ float g_Tx0[BB*NN*FF*TT];
__device__ float g_Tx1[BB*NN*FF*TT];
__device__ float g_Tx2[BB*NN*FF*TT];
__device__ float g_y[BB*NN*OO];
__device__ float g_stats[BB*2];

__device__ __forceinline__ float sigmoidf_(float v){ return 1.f/(1.f+__expf(-v)); }

// ---- ptx helpers (sm_80-generic) ----
__device__ __forceinline__ uint32_t smem_u32(const void* p){
    uint32_t a;
    asm("{ .reg .u64 t; cvta.to.shared.u64 t, %1; cvt.u32.u64 %0, t; }" : "=r"(a) : "l"(p));
    return a;
}
#define SWZ(o) ((uint32_t)(o) ^ ((((uint32_t)(o)) >> 3) & 0x70u))
__device__ __forceinline__ void cpa16(uint32_t dst, const void* src, bool p){
    int sz = p ? 16 : 0;
    asm volatile("cp.async.cg.shared.global [%0], [%1], 16, %2;" :: "r"(dst), "l"(src), "r"(sz) : "memory");
}
__device__ __forceinline__ void cpa_commit(){ asm volatile("cp.async.commit_group;" ::: "memory"); }
__device__ __forceinline__ void ldsm4(uint32_t* r, uint32_t addr){
    asm volatile("ldmatrix.sync.aligned.m8n8.x4.shared.b16 {%0,%1,%2,%3}, [%4];"
        : "=r"(r[0]),"=r"(r[1]),"=r"(r[2]),"=r"(r[3]) : "r"(addr));
}
__device__ __forceinline__ void ldsm2(uint32_t* r, uint32_t addr){
    asm volatile("ldmatrix.sync.aligned.m8n8.x2.shared.b16 {%0,%1}, [%2];"
        : "=r"(r[0]),"=r"(r[1]) : "r"(addr));
}
__device__ __forceinline__ void mma16816(float* c, const uint32_t* a, const uint32_t* b){
    asm volatile("mma.sync.aligned.m16n8k16.row.col.f32.bf16.bf16.f32 "
        "{%0,%1,%2,%3}, {%4,%5,%6,%7}, {%8,%9}, {%0,%1,%2,%3};"
        : "+f"(c[0]),"+f"(c[1]),"+f"(c[2]),"+f"(c[3])
        : "r"(a[0]),"r"(a[1]),"r"(a[2]),"r"(a[3]), "r"(b[0]),"r"(b[1]));
}

// ---- small kernels ----
__global__ void k_u2u3(const float* __restrict__ U2, const float* __restrict__ U3){
    int n = blockIdx.x*blockDim.x + threadIdx.x;
    if (n < NN){
        float s = 0.f;
        #pragma unroll
        for (int g=0; g<FF; g++) s += U2[g*NN+n]*U3[g];
        g_u2u3[n] = s;
    }
}
__global__ void k_tred(const float* __restrict__ x, const float* __restrict__ U1){
    int b = blockIdx.x >> 4, t = blockIdx.x & 15;
    int tid = threadIdx.x;
    float s1 = 0.f, s2 = 0.f;
    for (int i = tid; i < NN*FF; i += 256){
        int n = i >> 4, f = i & 15;
        float v = x[((size_t)(b*NN+n)*FF+f)*TT + t];
        s1 += v*U1[n]; s2 += v*g_u2u3[n];
    }
    __shared__ float r1[256], r2[256];
    r1[tid]=s1; r2[tid]=s2; __syncthreads();
    for (int o=128; o>0; o>>=1){
        if (tid<o){ r1[tid]+=r1[tid+o]; r2[tid]+=r2[tid+o]; }
        __syncthreads();
    }
    if (tid==0){ g_tlhs[b*TT+t]=r1[0]; g_trhs[b*TT+t]=r2[0]; }
}
__global__ void k_E(const float* __restrict__ Ve, const float* __restrict__ be){
    __shared__ float tl[BB*TT], tr[BB*TT], sVe[TT*TT], sbe[TT*TT], Eb[BB*TT*TT];
    int tid = threadIdx.x;
    if (tid < BB*TT){ tl[tid]=g_tlhs[tid]; tr[tid]=g_trhs[tid]; }
    if (tid < TT*TT){ sVe[tid]=Ve[tid]; sbe[tid]=be[tid]; }
    __syncthreads();
    for (int idx = tid; idx < BB*TT*TT; idx += 256){
        int b = idx>>8, t = (idx>>4)&15, r = idx&15;
        float s = 0.f;
        #pragma unroll
        for (int ss=0; ss<TT; ss++)
            s += sVe[t*TT+ss]*(1.f/(1.f+expf(-(tl[b*TT+ss]*tr[b*TT+r] + sbe[ss*TT+r]))));
        Eb[idx] = s;
    }
    __syncthreads();
    if (tid < BB*TT){
        int base = tid*TT;
        float m = -1e30f;
        for (int r=0;r<TT;r++) m = fmaxf(m, Eb[base+r]);
        float e[TT]; float sum = 0.f;
        for (int r=0;r<TT;r++){ e[r]=expf(Eb[base+r]-m); sum+=e[r]; }
        float inv = 1.f/sum;
        for (int r=0;r<TT;r++) g_E[base+r] = e[r]*inv;
    }
}
__global__ void k_xTAt(const float* __restrict__ x, const float* __restrict__ W1,
                       const float* __restrict__ W2, const float* __restrict__ W3){
    int bn = blockIdx.x;
    int b = bn / NN;
    int tid = threadIdx.x;
    __shared__ float xs[256], Es[256], sr0[16];
    xs[tid] = x[(size_t)bn*256 + tid];
    Es[tid] = g_E[b*256 + tid];
    __syncthreads();
    int f = tid >> 4, t = tid & 15;
    float s = 0.f;
    #pragma unroll
    for (int ss=0; ss<TT; ss++) s += Es[t*16+ss]*xs[f*16+ss];
    g_xTAt[(size_t)bn*256 + tid] = s;
    if (tid < 16){
        float a=0.f, c=0.f;
        #pragma unroll
        for (int t2=0;t2<16;t2++){ float v = xs[tid*16+t2]; a += v*W1[t2]; c += v*W3[t2]; }
        g_slhs[bn*16+tid] = a;
        sr0[tid] = c;
    }
    __syncthreads();
    if (tid < 16){
        float g = 0.f;
        #pragma unroll
        for (int kk=0;kk<16;kk++) g += W2[tid*16+kk]*sr0[kk];
        g_srhs[bn*16+tid] = g;
    }
}
__global__ void k_vs_split(const float* __restrict__ Vs){
    size_t i = (size_t)blockIdx.x*256 + threadIdx.x;
    if (i < (size_t)NN*NN){
        float v = Vs[i];
        __nv_bfloat16 h = __float2bfloat16(v);
        g_vs_h[i] = h;
        g_vs_l[i] = __float2bfloat16(v - __bfloat162float(h));
    }
}
__global__ void k_lap_split(const float* __restrict__ lap){
    size_t i = (size_t)blockIdx.x*256 + threadIdx.x;
    if (i < (size_t)NN*NN){
        float v = lap[i];
        __nv_bfloat16 h = __float2bfloat16(v);
        g_lap_h[i] = h;
        g_lap_l[i] = __float2bfloat16(v - __bfloat162float(h));
    }
}
// transpose-split: X [b][NN][256] fp32 -> XT [b][256][NN] bf16 h/l
__global__ void k_tsplit(const float* __restrict__ X){
    int b = blockIdx.z;
    int m0 = blockIdx.x*32, c0 = blockIdx.y*32;
    int tx = threadIdx.x & 31, ty = threadIdx.x >> 5;
    __shared__ float t[32][33];
    const float* Xb = X + (size_t)b*NN*256;
    #pragma unroll
    for (int i=0;i<4;i++){
        int row = ty + i*8;
        t[row][tx] = Xb[(size_t)(m0+row)*256 + c0 + tx];
    }
    __syncthreads();
    __nv_bfloat16* Th = g_bT_h + (size_t)b*256*NN;
    __nv_bfloat16* Tl = g_bT_l + (size_t)b*256*NN;
    #pragma unroll
    for (int i=0;i<4;i++){
        int row = ty + i*8;
        float v = t[tx][row];
        __nv_bfloat16 h = __float2bfloat16(v);
        size_t o = (size_t)(c0+row)*NN + m0 + tx;
        Th[o] = h;
        Tl[o] = __float2bfloat16(v - __bfloat162float(h));
    }
}
// sigmoid(prod+bs) - 0.5 (softmax shift-invariance), transposed [b][k][m], bf16 hi/lo
__global__ void k_sigP(const float* __restrict__ bs){
    int b = blockIdx.z;
    int m0 = blockIdx.y*32, k0 = blockIdx.x*32;
    int tid = threadIdx.x;
    __shared__ float Lm[32][17], Rk[32][17], sbs[32][33];
    for (int i = tid; i < 512; i += 256){
        int r = i>>4, c = i&15;
        Lm[r][c] = g_slhs[(b*NN + m0 + r)*16 + c];
        Rk[r][c] = g_srhs[(b*NN + k0 + r)*16 + c];
    }
    for (int i = tid; i < 1024; i += 256){
        int mi = i>>5, ki = i&31;
        sbs[mi][ki] = bs[(size_t)(m0+mi)*NN + k0 + ki];
    }
    __syncthreads();
    for (int e = tid; e < 1024; e += 256){
        int ki = e>>5, mi = e&31;
        float d = sbs[mi][ki];
        #pragma unroll
        for (int f=0; f<16; f++) d += Lm[mi][f]*Rk[ki][f];
        float s = sigmoidf_(d) - 0.5f;
        __nv_bfloat16 h = __float2bfloat16(s);
        size_t o = (size_t)b*NN*NN + (size_t)(k0+ki)*NN + (m0+mi);
        g_spT_h[o] = h;
        g_spT_l[o] = __float2bfloat16(s - __bfloat162float(h));
    }
}

#define KCHUNK 64
#define NCHUNK 63
#define NSTAGE 3
#define STG_BYTES 65536
#define OFF_AH 0
#define OFF_AL 16384
#define OFF_BH 32768
#define OFF_BL 49152
#define SMEM_REQ (NSTAGE*STG_BYTES + 1024)

// ---- big GEMM: 512 threads, 16 warps (4/SMSP), warp tile 32x32, 3-pass bf16 ----
__global__ void __launch_bounds__(512,1) gemm_S_mma(){
    extern __shared__ char dsm[];
    uint32_t sb = (smem_u32(dsm) + 1023u) & ~1023u;
    int tid = threadIdx.x, lane = tid&31, wid = tid>>5;
    int b = blockIdx.z;
    int mBase = blockIdx.y*128, nBase = blockIdx.x*128;
    int wm = wid>>2, wn = wid&3;

    const __nv_bfloat16* Ahp = g_vs_h;
    const __nv_bfloat16* Alp = g_vs_l;
    const __nv_bfloat16* Bhp = g_spT_h + (size_t)b*NN*NN;
    const __nv_bfloat16* Blp = g_spT_l + (size_t)b*NN*NN;

    float acc[2][4][4];
    #pragma unroll
    for (int i=0;i<2;i++)
        #pragma unroll
        for (int j=0;j<4;j++)
            #pragma unroll
            for (int q=0;q<4;q++) acc[i][j][q]=0.f;

    #define ISSUE_S(c_) do{ \
        int st_ = (c_)%NSTAGE; uint32_t stg_ = sb + st_*STG_BYTES; \
        int k0_ = (c_)*KCHUNK; \
        _Pragma("unroll") \
        for (int j_=0;j_<8;j_++){ \
            int op_ = j_*512 + tid; \
            int plane_ = op_>>10, row_ = (op_>>3)&127, seg_ = op_&7; \
            int kk_ = k0_ + seg_*8; \
            uint32_t dst_ = stg_ + plane_*16384 + SWZ(row_*128 + seg_*16); \
            const __nv_bfloat16* src_; bool v_; \
            if (plane_ < 2){ \
                v_ = (kk_ < NN) && ((mBase+row_) < NN); \
                src_ = (plane_ ? Alp : Ahp) + (size_t)(mBase+row_)*NN + kk_; \
            } else { \
                v_ = (kk_ < NN) && ((nBase+row_) < NN); \
                src_ = (plane_==2 ? Bhp : Blp) + (size_t)(nBase+row_)*NN + kk_; \
            } \
            cpa16(dst_, src_, v_); \
        } \
        cpa_commit(); \
    }while(0)

    ISSUE_S(0);
    ISSUE_S(1);
    ISSUE_S(2);

    for (int c=0;c<NCHUNK;c++){
        asm volatile("cp.async.wait_group 2;" ::: "memory");
        __syncthreads();
        uint32_t stg = sb + (c%NSTAGE)*STG_BYTES;
        #pragma unroll
        for (int ks=0;ks<4;ks++){
            uint32_t ah[2][4], al[2][4];
            #pragma unroll
            for (int mt=0;mt<2;mt++){
                int row = wm*32 + mt*16 + (lane&15);
                uint32_t bo = SWZ(row*128 + ks*32 + (lane>>4)*16);
                ldsm4(ah[mt], stg+OFF_AH+bo);
                ldsm4(al[mt], stg+OFF_AL+bo);
            }
            uint32_t bh[4][2], bl[4][2];
            #pragma unroll
            for (int nt=0;nt<4;nt++){
                int row = wn*32 + nt*8 + (lane&7);
                uint32_t bo = SWZ(row*128 + ks*32 + ((lane>>3)&1)*16);
                ldsm2(bh[nt], stg+OFF_BH+bo);
                ldsm2(bl[nt], stg+OFF_BL+bo);
            }
            #pragma unroll
            for (int mt=0;mt<2;mt++)
                #pragma unroll
                for (int nt=0;nt<4;nt++){
                    mma16816(acc[mt][nt], ah[mt], bh[nt]);
                    mma16816(acc[mt][nt], ah[mt], bl[nt]);
                    mma16816(acc[mt][nt], al[mt], bh[nt]);
                }
        }
        __syncthreads();
        if (c+NSTAGE < NCHUNK){ ISSUE_S(c+NSTAGE); }
        else { cpa_commit(); }
    }
    #undef ISSUE_S

    float* C = g_S + (size_t)b*NN*NN;
    int tig = lane&3, grp = lane>>2;
    #pragma unroll
    for (int mt=0;mt<2;mt++){
        int r0 = mBase + wm*32 + mt*16 + grp;
        int r1 = r0 + 8;
        #pragma unroll
        for (int nt=0;nt<4;nt++){
            int c0 = nBase + wn*32 + nt*8 + tig*2;
            if (c0 < NN){
                bool c1ok = (c0+1) < NN;
                if (r0 < NN){
                    C[(size_t)r0*NN + c0] = acc[mt][nt][0];
                    if (c1ok) C[(size_t)r0*NN + c0 + 1] = acc[mt][nt][1];
                }
                if (r1 < NN){
                    C[(size_t)r1*NN + c0] = acc[mt][nt][2];
                    if (c1ok) C[(size_t)r1*NN + c0 + 1] = acc[mt][nt][3];
                }
            }
        }
    }
}

// ---- generic bf16-split tensor GEMM (3-pass), 256 threads, for the small GEMMs ----
__global__ void __launch_bounds__(256,1) gemm_bsplit(
    const __nv_bfloat16* __restrict__ gAh, const __nv_bfloat16* __restrict__ gAl, long long sAb,
    const __nv_bfloat16* __restrict__ gBh, const __nv_bfloat16* __restrict__ gBl, long long sBb,
    float* __restrict__ gC, const float* __restrict__ gD, long long sCb,
    int ldc, int Ncols, float alpha, float beta)
{
    extern __shared__ char dsm[];
    uint32_t sb = (smem_u32(dsm) + 1023u) & ~1023u;
    int tid = threadIdx.x, lane = tid&31, wid = tid>>5;
    int b = blockIdx.z;
    int mBase = blockIdx.y*128, nBase = blockIdx.x*128;
    int wm = wid>>1, wn = wid&1;

    const __nv_bfloat16* Ahp = gAh + (size_t)b*sAb;
    const __nv_bfloat16* Alp = gAl + (size_t)b*sAb;
    const __nv_bfloat16* Bhp = gBh + (size_t)b*sBb;
    const __nv_bfloat16* Blp = gBl + (size_t)b*sBb;

    float acc[2][8][4];
    #pragma unroll
    for (int i=0;i<2;i++)
        #pragma unroll
        for (int j=0;j<8;j++)
            #pragma unroll
            for (int q=0;q<4;q++) acc[i][j][q]=0.f;

    #define ISSUE_STAGE(c_) do{ \
        int st_ = (c_)%NSTAGE; uint32_t stg_ = sb + st_*STG_BYTES; \
        int k0_ = (c_)*KCHUNK; \
        _Pragma("unroll") \
        for (int j_=0;j_<4;j_++){ \
            int op_ = j_*256+tid; int row_ = op_>>3, ch_ = op_&7; \
            int kk_ = k0_ + ch_*8; \
            uint32_t so_ = SWZ(row_*128 + ch_*16); \
            bool va_ = (kk_ < NN) && ((mBase+row_) < NN); \
            size_t ga_ = va_ ? ((size_t)(mBase+row_)*NN + kk_) : 0; \
            cpa16(stg_+OFF_AH+so_, Ahp+ga_, va_); \
            cpa16(stg_+OFF_AL+so_, Alp+ga_, va_); \
            bool vb_ = (kk_ < NN) && ((nBase+row_) < Ncols); \
            size_t gb_ = vb_ ? ((size_t)(nBase+row_)*NN + kk_) : 0; \
            cpa16(stg_+OFF_BH+so_, Bhp+gb_, vb_); \
            cpa16(stg_+OFF_BL+so_, Blp+gb_, vb_); \
        } \
        cpa_commit(); \
    }while(0)

    ISSUE_STAGE(0);
    ISSUE_STAGE(1);
    ISSUE_STAGE(2);

    for (int c=0;c<NCHUNK;c++){
        asm volatile("cp.async.wait_group 2;" ::: "memory");
        __syncthreads();
        uint32_t stg = sb + (c%NSTAGE)*STG_BYTES;
        #pragma unroll
        for (int ks=0;ks<4;ks++){
            uint32_t ah[2][4], al[2][4];
            #pragma unroll
            for (int mt=0;mt<2;mt++){
                int row = wm*32 + mt*16 + (lane&15);
                uint32_t bo = SWZ(row*128 + ks*32 + (lane>>4)*16);
                ldsm4(ah[mt], stg+OFF_AH+bo);
                ldsm4(al[mt], stg+OFF_AL+bo);
            }
            uint32_t bh[8][2], bl[8][2];
            #pragma unroll
            for (int nt=0;nt<8;nt++){
                int row = wn*64 + nt*8 + (lane&7);
                uint32_t bo = SWZ(row*128 + ks*32 + ((lane>>3)&1)*16);
                ldsm2(bh[nt], stg+OFF_BH+bo);
                ldsm2(bl[nt], stg+OFF_BL+bo);
            }
            #pragma unroll
            for (int mt=0;mt<2;mt++)
                #pragma unroll
                for (int nt=0;nt<8;nt++){
                    mma16816(acc[mt][nt], ah[mt], bh[nt]);
                    mma16816(acc[mt][nt], ah[mt], bl[nt]);
                    mma16816(acc[mt][nt], al[mt], bh[nt]);
                }
        }
        __syncthreads();
        if (c+NSTAGE < NCHUNK){ ISSUE_STAGE(c+NSTAGE); }
        else { cpa_commit(); }
    }
    #undef ISSUE_STAGE

    float* C = gC + (size_t)b*sCb;
    const float* D = gD ? gD + (size_t)b*sCb : (const float*)0;
    int tig = lane&3, grp = lane>>2;
    #pragma unroll
    for (int mt=0;mt<2;mt++){
        int r0 = mBase + wm*32 + mt*16 + grp;
        int r1 = r0 + 8;
        #pragma unroll
        for (int nt=0;nt<8;nt++){
            int c0 = nBase + wn*64 + nt*8 + tig*2;
            if (c0 < Ncols){
                bool c1ok = (c0+1) < Ncols;
                if (r0 < NN){
                    float v0 = alpha*acc[mt][nt][0];
                    if (D) v0 += beta*D[(size_t)r0*ldc + c0];
                    C[(size_t)r0*ldc + c0] = v0;
                    if (c1ok){
                        float v1 = alpha*acc[mt][nt][1];
                        if (D) v1 += beta*D[(size_t)r0*ldc + c0 + 1];
                        C[(size_t)r0*ldc + c0 + 1] = v1;
                    }
                }
                if (r1 < NN){
                    float v2 = alpha*acc[mt][nt][2];
                    if (D) v2 += beta*D[(size_t)r1*ldc + c0];
                    C[(size_t)r1*ldc + c0] = v2;
                    if (c1ok){
                        float v3 = alpha*acc[mt][nt][3];
                        if (D) v3 += beta*D[(size_t)r1*ldc + c0 + 1];
                        C[(size_t)r1*ldc + c0 + 1] = v3;
                    }
                }
            }
        }
    }
}

// softmax over last dim of S; writes bf16 h/l split (A operand of xSAtt)
__global__ void k_softmax(){
    __shared__ float row[NN];
    __shared__ float red[256];
    int tid = threadIdx.x;
    size_t base = (size_t)blockIdx.x * NN;
    float m = -1e30f;
    for (int i = tid; i < NN; i += 256){ float v = g_S[base+i]; row[i]=v; m = fmaxf(m,v); }
    red[tid]=m; __syncthreads();
    for (int o=128;o>0;o>>=1){ if (tid<o) red[tid]=fmaxf(red[tid],red[tid+o]); __syncthreads(); }
    m = red[0]; __syncthreads();
    float s = 0.f;
    for (int i = tid; i < NN; i += 256){ float e = __expf(row[i]-m); row[i]=e; s += e; }
    red[tid]=s; __syncthreads();
    for (int o=128;o>0;o>>=1){ if (tid<o) red[tid]+=red[tid+o]; __syncthreads(); }
    float inv = 1.f/red[0];
    for (int i = tid; i < NN; i += 256){
        float p = row[i]*inv;
        __nv_bfloat16 h = __float2bfloat16(p);
        g_spT_h[base+i] = h;
        g_spT_l[base+i] = __float2bfloat16(p - __bfloat162float(h));
    }
}

__global__ void k_final(const float* __restrict__ x, const float* __restrict__ cheb,
                        const float* __restrict__ tw, const float* __restrict__ tb){
    int bn = blockIdx.x;
    int tid = threadIdx.x;
    __shared__ float xs[256], t0[256], t1[256], t2[256], ts0[16], ts1[16], ts2[16];
    size_t rb = (size_t)bn*256;
    xs[tid]=x[rb+tid]; t0[tid]=g_Tx0[rb+tid]; t1[tid]=g_Tx1[rb+tid]; t2[tid]=g_Tx2[rb+tid];
    __syncthreads();
    if (tid < 48){
        int kk = tid>>4, f = tid&15;
        const float* src = (kk==0) ? t0 : ((kk==1) ? t1 : t2);
        float s = 0.f;
        #pragma unroll
        for (int t=0;t<16;t++) s += src[f*16+t];
        float* dst = (kk==0) ? ts0 : ((kk==1) ? ts1 : ts2);
        dst[f] = s;
    }
    __syncthreads();
    if (tid < 16){
        int o = tid;
        float tm = 0.f;
        #pragma unroll
        for (int c=0;c<16;c++)
            #pragma unroll
            for (int t=0;t<16;t++) tm += xs[c*16+t]*tw[(o*16+c)*16+t];
        float sp = 0.f;
        #pragma unroll
        for (int f=0;f<16;f++)
            sp += ts0[f]*cheb[f*16+o] + ts1[f]*cheb[256+f*16+o] + ts2[f]*cheb[512+f*16+o];
        g_y[bn*16+o] = sp*(1.f/16.f) + tm + tb[o] + xs[o*16+15];
    }
}

__global__ void k_stats(){
    int b = blockIdx.x, tid = threadIdx.x;
    double s = 0.0, ss = 0.0;
    for (int i = tid; i < NN*OO; i += 256){
        float v = g_y[b*NN*OO + i];
        s += (double)v; ss += (double)v*(double)v;
    }
    __shared__ double rs[256], rq[256];
    rs[tid]=s; rq[tid]=ss; __syncthreads();
    for (int o=128;o>0;o>>=1){ if (tid<o){ rs[tid]+=rs[tid+o]; rq[tid]+=rq[tid+o]; } __syncthreads(); }
    if (tid==0){
        double mean = rs[0]/(double)(NN*OO);
        double var  = rq[0]/(double)(NN*OO) - mean*mean;
        g_stats[b*2]   = (float)mean;
        g_stats[b*2+1] = (float)(1.0/sqrt(var + 1e-5));
    }
}
__global__ void k_out(const float* __restrict__ lng, const float* __restrict__ lnb,
                      float* __restrict__ out){
    int i = blockIdx.x*256 + threadIdx.x;
    if (i < BB*NN*OO){
        int b  = i / (NN*OO);
        int no = i % (NN*OO);
        float v = (g_y[i]-g_stats[b*2])*g_stats[b*2+1]*lng[no] + lnb[no];
        out[i] = fmaxf(v, 0.f);
    }
}

extern "C" void kernel_launch(void* const* d_in, const int* in_sizes, int n_in,
                              void* d_out, int out_size){
    const float* x    = (const float*)d_in[0];
    const float* lap  = (const float*)d_in[1];
    const float* W1   = (const float*)d_in[2];
    const float* W2   = (const float*)d_in[3];
    const float* W3   = (const float*)d_in[4];
    const float* bs   = (const float*)d_in[5];
    const float* Vs   = (const float*)d_in[6];
    const float* U1   = (const float*)d_in[7];
    const float* U2   = (const float*)d_in[8];
    const float* U3   = (const float*)d_in[9];
    const float* be   = (const float*)d_in[10];
    const float* Ve   = (const float*)d_in[11];
    const float* cheb = (const float*)d_in[12];
    const float* tw   = (const float*)d_in[13];
    const float* tb   = (const float*)d_in[14];
    const float* lng  = (const float*)d_in[15];
    const float* lnb  = (const float*)d_in[16];
    float* out = (float*)d_out;

    static int smem_set = 0;
    if (!smem_set){
        cudaFuncSetAttribute(gemm_bsplit, cudaFuncAttributeMaxDynamicSharedMemorySize, SMEM_REQ);
        cudaFuncSetAttribute(gemm_S_mma,  cudaFuncAttributeMaxDynamicSharedMemorySize, SMEM_REQ);
        smem_set = 1;
    }

    float *g_T0p, *g_T1p, *g_T2p, *g_xTp;
    __nv_bfloat16 *spT_h_p, *spT_l_p, *lap_h_p, *lap_l_p, *bT_h_p, *bT_l_p;
    cudaGetSymbolAddress((void**)&g_T0p, g_Tx0);
    cudaGetSymbolAddress((void**)&g_T1p, g_Tx1);
    cudaGetSymbolAddress((void**)&g_T2p, g_Tx2);
    cudaGetSymbolAddress((void**)&g_xTp, g_xTAt);
    cudaGetSymbolAddress((void**)&spT_h_p, g_spT_h);
    cudaGetSymbolAddress((void**)&spT_l_p, g_spT_l);
    cudaGetSymbolAddress((void**)&lap_h_p, g_lap_h);
    cudaGetSymbolAddress((void**)&lap_l_p, g_lap_l);
    cudaGetSymbolAddress((void**)&bT_h_p,  g_bT_h);
    cudaGetSymbolAddress((void**)&bT_l_p,  g_bT_l);

    k_u2u3<<<(NN+255)/256, 256>>>(U2, U3);
    k_tred<<<BB*TT, 256>>>(x, U1);
    k_E<<<1, 256>>>(Ve, be);
    k_xTAt<<<BB*NN, 256>>>(x, W1, W2, W3);
    k_vs_split<<<(NN*NN+255)/256, 256>>>(Vs);
    k_lap_split<<<(NN*NN+255)/256, 256>>>(lap);
    k_sigP<<<dim3(125,125,BB), 256>>>(bs);

    // S = Vs @ sigP'   (big GEMM, 512-thread high-occupancy version)
    gemm_S_mma<<<dim3(32,32,BB), 512, SMEM_REQ>>>();

    k_softmax<<<BB*NN, 256>>>();
    k_tsplit<<<dim3(125,8,BB), 256>>>(g_xTp);

    gemm_bsplit<<<dim3(2,32,BB), 256, SMEM_REQ>>>(
        spT_h_p, spT_l_p, (long long)NN*NN, bT_h_p, bT_l_p, (long long)256*NN,
        g_T0p, (const float*)0, (long long)NN*256, 256, 256, 1.f, 0.f);

    k_tsplit<<<dim3(125,8,BB), 256>>>(g_T0p);

    gemm_bsplit<<<dim3(2,32,BB), 256, SMEM_REQ>>>(
        lap_h_p, lap_l_p, 0LL, bT_h_p, bT_l_p, (long long)256*NN,
        g_T1p, (const float*)0, (long long)NN*256, 256, 256, 1.f, 0.f);

    k_tsplit<<<dim3(125,8,BB), 256>>>(g_T1p);

    gemm_bsplit<<<dim3(2,32,BB), 256, SMEM_REQ>>>(
        lap_h_p, lap_l_p, 0LL, bT_h_p, bT_l_p, (long long)256*NN,
        g_T2p, g_T0p, (long long)NN*256, 256, 256, 2.f, -1.f);

    k_final<<<BB*NN, 256>>>(x, cheb, tw, tb);
    k_stats<<<BB, 256>>>();
    k_out<<<(BB*NN*OO+255)/256, 256>>>(lng, lnb, out);
}

// round 10
// speedup vs baseline: 2.6211x; 1.1585x over previous
#include <cuda_runtime.h>
#include <cuda_bf16.h>
#include <math.h>
#include <stdint.h>

#define NN 4000
#define BB 4
#define FF 16
#define TT 16
#define OO 16

__device__ float g_u2u3[NN];
__device__ float g_tlhs[BB*TT];
__device__ float g_trhs[BB*TT];
__device__ float g_E[BB*TT*TT];
__device__ float g_xTAt[BB*NN*FF*TT];
__device__ float g_slhs[BB*NN*FF];
__device__ float g_srhs[BB*NN*FF];
// pre-swizzled chunk-tiled GEMM operands (zero-init by CUDA => padding stays 0)
// A (Vs h/l): [yb 0..31][chunk 0..62][ h 16KB | l 16KB ]
__device__ __align__(256) unsigned char g_At[(size_t)32*63*32768];
// B (sigP^T h/l): [b][xb 0..31][chunk 0..62][ h 16KB | l 16KB ]
__device__ __align__(256) unsigned char g_Bt[(size_t)BB*32*63*32768];
__device__ __align__(256) __nv_bfloat16 g_spT_h[(size_t)BB*NN*NN]; // softmaxed S split (A of xSAtt)
__device__ __align__(256) __nv_bfloat16 g_spT_l[(size_t)BB*NN*NN];
__device__ __align__(256) __nv_bfloat16 g_lap_h[(size_t)NN*NN];
__device__ __align__(256) __nv_bfloat16 g_lap_l[(size_t)NN*NN];
__device__ __align__(256) __nv_bfloat16 g_bT_h[(size_t)BB*256*NN];  // transposed B panels
__device__ __align__(256) __nv_bfloat16 g_bT_l[(size_t)BB*256*NN];
__device__ __align__(256) float g_S[(size_t)BB*NN*NN];
__device__ float g_Tx0[BB*NN*FF*TT];
__device__ float g_Tx1[BB*NN*FF*TT];
__device__ float g_Tx2[BB*NN*FF*TT];
__device__ float g_y[BB*NN*OO];
__device__ float g_stats[BB*2];

__device__ __forceinline__ float sigmoidf_(float v){ return 1.f/(1.f+__expf(-v)); }

// ---- ptx helpers ----
__device__ __forceinline__ uint32_t smem_u32(const void* p){
    uint32_t a;
    asm("{ .reg .u64 t; cvta.to.shared.u64 t, %1; cvt.u32.u64 %0, t; }" : "=r"(a) : "l"(p));
    return a;
}
#define SWZ(o) ((uint32_t)(o) ^ ((((uint32_t)(o)) >> 3) & 0x70u))
__device__ __forceinline__ void cpa16(uint32_t dst, const void* src, bool p){
    int sz = p ? 16 : 0;
    asm volatile("cp.async.cg.shared.global [%0], [%1], 16, %2;" :: "r"(dst), "l"(src), "r"(sz) : "memory");
}
__device__ __forceinline__ void cpa_commit(){ asm volatile("cp.async.commit_group;" ::: "memory"); }
__device__ __forceinline__ void ldsm4(uint32_t* r, uint32_t addr){
    asm volatile("ldmatrix.sync.aligned.m8n8.x4.shared.b16 {%0,%1,%2,%3}, [%4];"
        : "=r"(r[0]),"=r"(r[1]),"=r"(r[2]),"=r"(r[3]) : "r"(addr));
}
__device__ __forceinline__ void ldsm2(uint32_t* r, uint32_t addr){
    asm volatile("ldmatrix.sync.aligned.m8n8.x2.shared.b16 {%0,%1}, [%2];"
        : "=r"(r[0]),"=r"(r[1]) : "r"(addr));
}
__device__ __forceinline__ void mma16816(float* c, const uint32_t* a, const uint32_t* b){
    asm volatile("mma.sync.aligned.m16n8k16.row.col.f32.bf16.bf16.f32 "
        "{%0,%1,%2,%3}, {%4,%5,%6,%7}, {%8,%9}, {%0,%1,%2,%3};"
        : "+f"(c[0]),"+f"(c[1]),"+f"(c[2]),"+f"(c[3])
        : "r"(a[0]),"r"(a[1]),"r"(a[2]),"r"(a[3]), "r"(b[0]),"r"(b[1]));
}
__device__ __forceinline__ void mbar_init(uint32_t a, uint32_t cnt){
    asm volatile("mbarrier.init.shared.b64 [%0], %1;" :: "r"(a), "r"(cnt) : "memory");
}
__device__ __forceinline__ void mbar_expect_tx(uint32_t a, uint32_t bytes){
    asm volatile("mbarrier.arrive.expect_tx.shared.b64 _, [%0], %1;" :: "r"(a), "r"(bytes) : "memory");
}
__device__ __forceinline__ void mbar_wait(uint32_t a, uint32_t ph){
    uint32_t done;
    asm volatile("{\n\t.reg .pred p;\n\t"
        "mbarrier.try_wait.parity.acquire.cta.shared::cta.b64 p, [%1], %2;\n\t"
        "selp.b32 %0, 1, 0, p;\n\t}" : "=r"(done) : "r"(a), "r"(ph) : "memory");
    if (!done){
        asm volatile("{\n\t.reg .pred P1;\n\t"
            "WL%=:\n\t"
            "mbarrier.try_wait.parity.acquire.cta.shared::cta.b64 P1, [%0], %1, 0x989680;\n\t"
            "@P1 bra.uni WD%=;\n\t"
            "bra.uni WL%=;\n\t"
            "WD%=:\n\t}" :: "r"(a), "r"(ph) : "memory");
    }
}
__device__ __forceinline__ void tma_bulk_g2s(uint32_t dst, const void* src, uint32_t bytes, uint32_t mbar){
    asm volatile("cp.async.bulk.shared::cluster.global.mbarrier::complete_tx::bytes [%0], [%1], %2, [%3];"
        :: "r"(dst), "l"(src), "r"(bytes), "r"(mbar) : "memory");
}

// ---- small kernels ----
__global__ void k_u2u3(const float* __restrict__ U2, const float* __restrict__ U3){
    int n = blockIdx.x*blockDim.x + threadIdx.x;
    if (n < NN){
        float s = 0.f;
        #pragma unroll
        for (int g=0; g<FF; g++) s += U2[g*NN+n]*U3[g];
        g_u2u3[n] = s;
    }
}
__global__ void k_tred(const float* __restrict__ x, const float* __restrict__ U1){
    int b = blockIdx.x >> 4, t = blockIdx.x & 15;
    int tid = threadIdx.x;
    float s1 = 0.f, s2 = 0.f;
    for (int i = tid; i < NN*FF; i += 256){
        int n = i >> 4, f = i & 15;
        float v = x[((size_t)(b*NN+n)*FF+f)*TT + t];
        s1 += v*U1[n]; s2 += v*g_u2u3[n];
    }
    __shared__ float r1[256], r2[256];
    r1[tid]=s1; r2[tid]=s2; __syncthreads();
    for (int o=128; o>0; o>>=1){
        if (tid<o){ r1[tid]+=r1[tid+o]; r2[tid]+=r2[tid+o]; }
        __syncthreads();
    }
    if (tid==0){ g_tlhs[b*TT+t]=r1[0]; g_trhs[b*TT+t]=r2[0]; }
}
__global__ void k_E(const float* __restrict__ Ve, const float* __restrict__ be){
    __shared__ float tl[BB*TT], tr[BB*TT], sVe[TT*TT], sbe[TT*TT], Eb[BB*TT*TT];
    int tid = threadIdx.x;
    if (tid < BB*TT){ tl[tid]=g_tlhs[tid]; tr[tid]=g_trhs[tid]; }
    if (tid < TT*TT){ sVe[tid]=Ve[tid]; sbe[tid]=be[tid]; }
    __syncthreads();
    for (int idx = tid; idx < BB*TT*TT; idx += 256){
        int b = idx>>8, t = (idx>>4)&15, r = idx&15;
        float s = 0.f;
        #pragma unroll
        for (int ss=0; ss<TT; ss++)
            s += sVe[t*TT+ss]*(1.f/(1.f+expf(-(tl[b*TT+ss]*tr[b*TT+r] + sbe[ss*TT+r]))));
        Eb[idx] = s;
    }
    __syncthreads();
    if (tid < BB*TT){
        int base = tid*TT;
        float m = -1e30f;
        for (int r=0;r<TT;r++) m = fmaxf(m, Eb[base+r]);
        float e[TT]; float sum = 0.f;
        for (int r=0;r<TT;r++){ e[r]=expf(Eb[base+r]-m); sum+=e[r]; }
        float inv = 1.f/sum;
        for (int r=0;r<TT;r++) g_E[base+r] = e[r]*inv;
    }
}
__global__ void k_xTAt(const float* __restrict__ x, const float* __restrict__ W1,
                       const float* __restrict__ W2, const float* __restrict__ W3){
    int bn = blockIdx.x;
    int b = bn / NN;
    int tid = threadIdx.x;
    __shared__ float xs[256], Es[256], sr0[16];
    xs[tid] = x[(size_t)bn*256 + tid];
    Es[tid] = g_E[b*256 + tid];
    __syncthreads();
    int f = tid >> 4, t = tid & 15;
    float s = 0.f;
    #pragma unroll
    for (int ss=0; ss<TT; ss++) s += Es[t*16+ss]*xs[f*16+ss];
    g_xTAt[(size_t)bn*256 + tid] = s;
    if (tid < 16){
        float a=0.f, c=0.f;
        #pragma unroll
        for (int t2=0;t2<16;t2++){ float v = xs[tid*16+t2]; a += v*W1[t2]; c += v*W3[t2]; }
        g_slhs[bn*16+tid] = a;
        sr0[tid] = c;
    }
    __syncthreads();
    if (tid < 16){
        float g = 0.f;
        #pragma unroll
        for (int kk=0;kk<16;kk++) g += W2[tid*16+kk]*sr0[kk];
        g_srhs[bn*16+tid] = g;
    }
}
// split (Vs) into bf16 h/l, written directly in the tiled+swizzled GEMM layout
__global__ void k_vs_tiled(const float* __restrict__ Vs){
    size_t i = (size_t)blockIdx.x*256 + threadIdx.x;
    if (i < (size_t)NN*NN){
        int n = (int)(i / NN), m = (int)(i % NN);
        float v = Vs[i];
        __nv_bfloat16 h = __float2bfloat16(v);
        __nv_bfloat16 l = __float2bfloat16(v - __bfloat162float(h));
        int yb = n>>7, r = n&127, ch = m>>6, sg = m&63;
        size_t tb = ((size_t)yb*63 + ch)*32768;
        uint32_t off = SWZ((uint32_t)(r*128 + sg*2));
        *(__nv_bfloat16*)(g_At + tb + off) = h;
        *(__nv_bfloat16*)(g_At + tb + 16384 + off) = l;
    }
}
__global__ void k_lap_split(const float* __restrict__ lap){
    size_t i = (size_t)blockIdx.x*256 + threadIdx.x;
    if (i < (size_t)NN*NN){
        float v = lap[i];
        __nv_bfloat16 h = __float2bfloat16(v);
        g_lap_h[i] = h;
        g_lap_l[i] = __float2bfloat16(v - __bfloat162float(h));
    }
}
// transpose-split: X [b][NN][256] fp32 -> XT [b][256][NN] bf16 h/l
__global__ void k_tsplit(const float* __restrict__ X){
    int b = blockIdx.z;
    int m0 = blockIdx.x*32, c0 = blockIdx.y*32;
    int tx = threadIdx.x & 31, ty = threadIdx.x >> 5;
    __shared__ float t[32][33];
    const float* Xb = X + (size_t)b*NN*256;
    #pragma unroll
    for (int i=0;i<4;i++){
        int row = ty + i*8;
        t[row][tx] = Xb[(size_t)(m0+row)*256 + c0 + tx];
    }
    __syncthreads();
    __nv_bfloat16* Th = g_bT_h + (size_t)b*256*NN;
    __nv_bfloat16* Tl = g_bT_l + (size_t)b*256*NN;
    #pragma unroll
    for (int i=0;i<4;i++){
        int row = ty + i*8;
        float v = t[tx][row];
        __nv_bfloat16 h = __float2bfloat16(v);
        size_t o = (size_t)(c0+row)*NN + m0 + tx;
        Th[o] = h;
        Tl[o] = __float2bfloat16(v - __bfloat162float(h));
    }
}
// sigmoid(prod+bs) - 0.5, written as bf16 h/l into the tiled+swizzled B layout [b][xb][ch]
__global__ void k_sigP(const float* __restrict__ bs){
    int b = blockIdx.z;
    int m0 = blockIdx.y*32, k0 = blockIdx.x*32;
    int tid = threadIdx.x;
    __shared__ float Lm[32][17], Rk[32][17], sbs[32][33];
    for (int i = tid; i < 512; i += 256){
        int r = i>>4, c = i&15;
        Lm[r][c] = g_slhs[(b*NN + m0 + r)*16 + c];
        Rk[r][c] = g_srhs[(b*NN + k0 + r)*16 + c];
    }
    for (int i = tid; i < 1024; i += 256){
        int mi = i>>5, ki = i&31;
        sbs[mi][ki] = bs[(size_t)(m0+mi)*NN + k0 + ki];
    }
    __syncthreads();
    for (int e = tid; e < 1024; e += 256){
        int ki = e>>5, mi = e&31;
        float d = sbs[mi][ki];
        #pragma unroll
        for (int f=0; f<16; f++) d += Lm[mi][f]*Rk[ki][f];
        float s = sigmoidf_(d) - 0.5f;
        __nv_bfloat16 h = __float2bfloat16(s);
        __nv_bfloat16 l = __float2bfloat16(s - __bfloat162float(h));
        int kg = k0 + ki;       // output-col index of S (tile row)
        int mg = m0 + mi;       // contraction index
        int xb = kg>>7, r = kg&127, ch = mg>>6, sg = mg&63;
        size_t tb = ((size_t)(b*32 + xb)*63 + ch)*32768;
        uint32_t off = SWZ((uint32_t)(r*128 + sg*2));
        *(__nv_bfloat16*)(g_Bt + tb + off) = h;
        *(__nv_bfloat16*)(g_Bt + tb + 16384 + off) = l;
    }
}

#define KCHUNK 64
#define NCHUNK 63
#define NSTAGE 3
#define STG_BYTES 65536
#define OFF_AH 0
#define OFF_AL 16384
#define OFF_BH 32768
#define OFF_BL 49152
#define SMEM_REQ (NSTAGE*STG_BYTES + 1024)
#define SMEM_REQ_S (NSTAGE*STG_BYTES + 2048)

// ---- big GEMM: bulk-TMA loads (2 copies/chunk), proven R6 mma/epilogue ----
__global__ void __launch_bounds__(256,1) gemm_S_mma(){
    extern __shared__ char dsm[];
    uint32_t sb = (smem_u32(dsm) + 1023u) & ~1023u;
    uint32_t mb = sb + NSTAGE*STG_BYTES;   // 3 mbarriers, 8B each
    int tid = threadIdx.x, lane = tid&31, wid = tid>>5;
    int b = blockIdx.z;
    int yb = blockIdx.y, xb = blockIdx.x;
    int mBase = yb*128, nBase = xb*128;
    int wm = wid>>1, wn = wid&1;

    const unsigned char* Asrc = g_At + (size_t)yb*63*32768;
    const unsigned char* Bsrc = g_Bt + ((size_t)(b*32 + xb))*63*32768;

    if (tid==0){
        mbar_init(mb,1); mbar_init(mb+8,1); mbar_init(mb+16,1);
    }
    __syncthreads();
    if (tid==0){
        #pragma unroll
        for (int p=0;p<NSTAGE;p++){
            uint32_t bar = mb + p*8;
            mbar_expect_tx(bar, 65536);
            tma_bulk_g2s(sb + p*STG_BYTES,          Asrc + (size_t)p*32768, 32768, bar);
            tma_bulk_g2s(sb + p*STG_BYTES + 32768,  Bsrc + (size_t)p*32768, 32768, bar);
        }
    }

    float acc[2][8][4];
    #pragma unroll
    for (int i=0;i<2;i++)
        #pragma unroll
        for (int j=0;j<8;j++)
            #pragma unroll
            for (int q=0;q<4;q++) acc[i][j][q]=0.f;

    for (int c=0;c<NCHUNK;c++){
        int s = c%NSTAGE;
        mbar_wait(mb + s*8, (uint32_t)((c/NSTAGE)&1));
        uint32_t stg = sb + s*STG_BYTES;
        #pragma unroll
        for (int ks=0;ks<4;ks++){
            uint32_t ah[2][4], al[2][4];
            #pragma unroll
            for (int mt=0;mt<2;mt++){
                int row = wm*32 + mt*16 + (lane&15);
                uint32_t bo = SWZ(row*128 + ks*32 + (lane>>4)*16);
                ldsm4(ah[mt], stg+OFF_AH+bo);
                ldsm4(al[mt], stg+OFF_AL+bo);
            }
            uint32_t bh[8][2], bl[8][2];
            #pragma unroll
            for (int nt=0;nt<8;nt++){
                int row = wn*64 + nt*8 + (lane&7);
                uint32_t bo = SWZ(row*128 + ks*32 + ((lane>>3)&1)*16);
                ldsm2(bh[nt], stg+OFF_BH+bo);
                ldsm2(bl[nt], stg+OFF_BL+bo);
            }
            #pragma unroll
            for (int mt=0;mt<2;mt++)
                #pragma unroll
                for (int nt=0;nt<8;nt++){
                    mma16816(acc[mt][nt], ah[mt], bh[nt]);
                    mma16816(acc[mt][nt], ah[mt], bl[nt]);
                    mma16816(acc[mt][nt], al[mt], bh[nt]);
                }
        }
        __syncthreads();
        if (tid==0 && (c+NSTAGE) < NCHUNK){
            int cn = c+NSTAGE;
            uint32_t bar = mb + s*8;
            mbar_expect_tx(bar, 65536);
            tma_bulk_g2s(stg,          Asrc + (size_t)cn*32768, 32768, bar);
            tma_bulk_g2s(stg + 32768,  Bsrc + (size_t)cn*32768, 32768, bar);
        }
    }

    float* C = g_S + (size_t)b*NN*NN;
    int tig = lane&3, grp = lane>>2;
    #pragma unroll
    for (int mt=0;mt<2;mt++){
        int r0 = mBase + wm*32 + mt*16 + grp;
        int r1 = r0 + 8;
        #pragma unroll
        for (int nt=0;nt<8;nt++){
            int c0 = nBase + wn*64 + nt*8 + tig*2;
            if (c0 < NN){
                bool c1ok = (c0+1) < NN;
                if (r0 < NN){
                    C[(size_t)r0*NN + c0] = acc[mt][nt][0];
                    if (c1ok) C[(size_t)r0*NN + c0 + 1] = acc[mt][nt][1];
                }
                if (r1 < NN){
                    C[(size_t)r1*NN + c0] = acc[mt][nt][2];
                    if (c1ok) C[(size_t)r1*NN + c0 + 1] = acc[mt][nt][3];
                }
            }
        }
    }
}

// ---- generic bf16-split tensor GEMM (3-pass), 256 threads, for the small GEMMs ----
__global__ void __launch_bounds__(256,1) gemm_bsplit(
    const __nv_bfloat16* __restrict__ gAh, const __nv_bfloat16* __restrict__ gAl, long long sAb,
    const __nv_bfloat16* __restrict__ gBh, const __nv_bfloat16* __restrict__ gBl, long long sBb,
    float* __restrict__ gC, const float* __restrict__ gD, long long sCb,
    int ldc, int Ncols, float alpha, float beta)
{
    extern __shared__ char dsm[];
    uint32_t sb = (smem_u32(dsm) + 1023u) & ~1023u;
    int tid = threadIdx.x, lane = tid&31, wid = tid>>5;
    int b = blockIdx.z;
    int mBase = blockIdx.y*128, nBase = blockIdx.x*128;
    int wm = wid>>1, wn = wid&1;

    const __nv_bfloat16* Ahp = gAh + (size_t)b*sAb;
    const __nv_bfloat16* Alp = gAl + (size_t)b*sAb;
    const __nv_bfloat16* Bhp = gBh + (size_t)b*sBb;
    const __nv_bfloat16* Blp = gBl + (size_t)b*sBb;

    float acc[2][8][4];
    #pragma unroll
    for (int i=0;i<2;i++)
        #pragma unroll
        for (int j=0;j<8;j++)
            #pragma unroll
            for (int q=0;q<4;q++) acc[i][j][q]=0.f;

    #define ISSUE_STAGE(c_) do{ \
        int st_ = (c_)%NSTAGE; uint32_t stg_ = sb + st_*STG_BYTES; \
        int k0_ = (c_)*KCHUNK; \
        _Pragma("unroll") \
        for (int j_=0;j_<4;j_++){ \
            int op_ = j_*256+tid; int row_ = op_>>3, ch_ = op_&7; \
            int kk_ = k0_ + ch_*8; \
            uint32_t so_ = SWZ(row_*128 + ch_*16); \
            bool va_ = (kk_ < NN) && ((mBase+row_) < NN); \
            size_t ga_ = va_ ? ((size_t)(mBase+row_)*NN + kk_) : 0; \
            cpa16(stg_+OFF_AH+so_, Ahp+ga_, va_); \
            cpa16(stg_+OFF_AL+so_, Alp+ga_, va_); \
            bool vb_ = (kk_ < NN) && ((nBase+row_) < Ncols); \
            size_t gb_ = vb_ ? ((size_t)(nBase+row_)*NN + kk_) : 0; \
            cpa16(stg_+OFF_BH+so_, Bhp+gb_, vb_); \
            cpa16(stg_+OFF_BL+so_, Blp+gb_, vb_); \
        } \
        cpa_commit(); \
    }while(0)

    ISSUE_STAGE(0);
    ISSUE_STAGE(1);
    ISSUE_STAGE(2);

    for (int c=0;c<NCHUNK;c++){
        asm volatile("cp.async.wait_group 2;" ::: "memory");
        __syncthreads();
        uint32_t stg = sb + (c%NSTAGE)*STG_BYTES;
        #pragma unroll
        for (int ks=0;ks<4;ks++){
            uint32_t ah[2][4], al[2][4];
            #pragma unroll
            for (int mt=0;mt<2;mt++){
                int row = wm*32 + mt*16 + (lane&15);
                uint32_t bo = SWZ(row*128 + ks*32 + (lane>>4)*16);
                ldsm4(ah[mt], stg+OFF_AH+bo);
                ldsm4(al[mt], stg+OFF_AL+bo);
            }
            uint32_t bh[8][2], bl[8][2];
            #pragma unroll
            for (int nt=0;nt<8;nt++){
                int row = wn*64 + nt*8 + (lane&7);
                uint32_t bo = SWZ(row*128 + ks*32 + ((lane>>3)&1)*16);
                ldsm2(bh[nt], stg+OFF_BH+bo);
                ldsm2(bl[nt], stg+OFF_BL+bo);
            }
            #pragma unroll
            for (int mt=0;mt<2;mt++)
                #pragma unroll
                for (int nt=0;nt<8;nt++){
                    mma16816(acc[mt][nt], ah[mt], bh[nt]);
                    mma16816(acc[mt][nt], ah[mt], bl[nt]);
                    mma16816(acc[mt][nt], al[mt], bh[nt]);
                }
        }
        __syncthreads();
        if (c+NSTAGE < NCHUNK){ ISSUE_STAGE(c+NSTAGE); }
        else { cpa_commit(); }
    }
    #undef ISSUE_STAGE

    float* C = gC + (size_t)b*sCb;
    const float* D = gD ? gD + (size_t)b*sCb : (const float*)0;
    int tig = lane&3, grp = lane>>2;
    #pragma unroll
    for (int mt=0;mt<2;mt++){
        int r0 = mBase + wm*32 + mt*16 + grp;
        int r1 = r0 + 8;
        #pragma unroll
        for (int nt=0;nt<8;nt++){
            int c0 = nBase + wn*64 + nt*8 + tig*2;
            if (c0 < Ncols){
                bool c1ok = (c0+1) < Ncols;
                if (r0 < NN){
                    float v0 = alpha*acc[mt][nt][0];
                    if (D) v0 += beta*D[(size_t)r0*ldc + c0];
                    C[(size_t)r0*ldc + c0] = v0;
                    if (c1ok){
                        float v1 = alpha*acc[mt][nt][1];
                        if (D) v1 += beta*D[(size_t)r0*ldc + c0 + 1];
                        C[(size_t)r0*ldc + c0 + 1] = v1;
                    }
                }
                if (r1 < NN){
                    float v2 = alpha*acc[mt][nt][2];
                    if (D) v2 += beta*D[(size_t)r1*ldc + c0];
                    C[(size_t)r1*ldc + c0] = v2;
                    if (c1ok){
                        float v3 = alpha*acc[mt][nt][3];
                        if (D) v3 += beta*D[(size_t)r1*ldc + c0 + 1];
                        C[(size_t)r1*ldc + c0 + 1] = v3;
                    }
                }
            }
        }
    }
}

// softmax over last dim of S; writes bf16 h/l split (A operand of xSAtt)
__global__ void k_softmax(){
    __shared__ float row[NN];
    __shared__ float red[256];
    int tid = threadIdx.x;
    size_t base = (size_t)blockIdx.x * NN;
    float m = -1e30f;
    for (int i = tid; i < NN; i += 256){ float v = g_S[base+i]; row[i]=v; m = fmaxf(m,v); }
    red[tid]=m; __syncthreads();
    for (int o=128;o>0;o>>=1){ if (tid<o) red[tid]=fmaxf(red[tid],red[tid+o]); __syncthreads(); }
    m = red[0]; __syncthreads();
    float s = 0.f;
    for (int i = tid; i < NN; i += 256){ float e = __expf(row[i]-m); row[i]=e; s += e; }
    red[tid]=s; __syncthreads();
    for (int o=128;o>0;o>>=1){ if (tid<o) red[tid]+=red[tid+o]; __syncthreads(); }
    float inv = 1.f/red[0];
    for (int i = tid; i < NN; i += 256){
        float p = row[i]*inv;
        __nv_bfloat16 h = __float2bfloat16(p);
        g_spT_h[base+i] = h;
        g_spT_l[base+i] = __float2bfloat16(p - __bfloat162float(h));
    }
}

__global__ void k_final(const float* __restrict__ x, const float* __restrict__ cheb,
                        const float* __restrict__ tw, const float* __restrict__ tb){
    int bn = blockIdx.x;
    int tid = threadIdx.x;
    __shared__ float xs[256], t0[256], t1[256], t2[256], ts0[16], ts1[16], ts2[16];
    size_t rb = (size_t)bn*256;
    xs[tid]=x[rb+tid]; t0[tid]=g_Tx0[rb+tid]; t1[tid]=g_Tx1[rb+tid]; t2[tid]=g_Tx2[rb+tid];
    __syncthreads();
    if (tid < 48){
        int kk = tid>>4, f = tid&15;
        const float* src = (kk==0) ? t0 : ((kk==1) ? t1 : t2);
        float s = 0.f;
        #pragma unroll
        for (int t=0;t<16;t++) s += src[f*16+t];
        float* dst = (kk==0) ? ts0 : ((kk==1) ? ts1 : ts2);
        dst[f] = s;
    }
    __syncthreads();
    if (tid < 16){
        int o = tid;
        float tm = 0.f;
        #pragma unroll
        for (int c=0;c<16;c++)
            #pragma unroll
            for (int t=0;t<16;t++) tm += xs[c*16+t]*tw[(o*16+c)*16+t];
        float sp = 0.f;
        #pragma unroll
        for (int f=0;f<16;f++)
            sp += ts0[f]*cheb[f*16+o] + ts1[f]*cheb[256+f*16+o] + ts2[f]*cheb[512+f*16+o];
        g_y[bn*16+o] = sp*(1.f/16.f) + tm + tb[o] + xs[o*16+15];
    }
}

__global__ void k_stats(){
    int b = blockIdx.x, tid = threadIdx.x;
    double s = 0.0, ss = 0.0;
    for (int i = tid; i < NN*OO; i += 256){
        float v = g_y[b*NN*OO + i];
        s += (double)v; ss += (double)v*(double)v;
    }
    __shared__ double rs[256], rq[256];
    rs[tid]=s; rq[tid]=ss; __syncthreads();
    for (int o=128;o>0;o>>=1){ if (tid<o){ rs[tid]+=rs[tid+o]; rq[tid]+=rq[tid+o]; } __syncthreads(); }
    if (tid==0){
        double mean = rs[0]/(double)(NN*OO);
        double var  = rq[0]/(double)(NN*OO) - mean*mean;
        g_stats[b*2]   = (float)mean;
        g_stats[b*2+1] = (float)(1.0/sqrt(var + 1e-5));
    }
}
__global__ void k_out(const float* __restrict__ lng, const float* __restrict__ lnb,
                      float* __restrict__ out){
    int i = blockIdx.x*256 + threadIdx.x;
    if (i < BB*NN*OO){
        int b  = i / (NN*OO);
        int no = i % (NN*OO);
        float v = (g_y[i]-g_stats[b*2])*g_stats[b*2+1]*lng[no] + lnb[no];
        out[i] = fmaxf(v, 0.f);
    }
}

extern "C" void kernel_launch(void* const* d_in, const int* in_sizes, int n_in,
                              void* d_out, int out_size){
    const float* x    = (const float*)d_in[0];
    const float* lap  = (const float*)d_in[1];
    const float* W1   = (const float*)d_in[2];
    const float* W2   = (const float*)d_in[3];
    const float* W3   = (const float*)d_in[4];
    const float* bs   = (const float*)d_in[5];
    const float* Vs   = (const float*)d_in[6];
    const float* U1   = (const float*)d_in[7];
    const float* U2   = (const float*)d_in[8];
    const float* U3   = (const float*)d_in[9];
    const float* be   = (const float*)d_in[10];
    const float* Ve   = (const float*)d_in[11];
    const float* cheb = (const float*)d_in[12];
    const float* tw   = (const float*)d_in[13];
    const float* tb   = (const float*)d_in[14];
    const float* lng  = (const float*)d_in[15];
    const float* lnb  = (const float*)d_in[16];
    float* out = (float*)d_out;

    static int smem_set = 0;
    if (!smem_set){
        cudaFuncSetAttribute(gemm_bsplit, cudaFuncAttributeMaxDynamicSharedMemorySize, SMEM_REQ);
        cudaFuncSetAttribute(gemm_S_mma,  cudaFuncAttributeMaxDynamicSharedMemorySize, SMEM_REQ_S);
        smem_set = 1;
    }

    float *g_T0p, *g_T1p, *g_T2p, *g_xTp;
    __nv_bfloat16 *spT_h_p, *spT_l_p, *lap_h_p, *lap_l_p, *bT_h_p, *bT_l_p;
    cudaGetSymbolAddress((void**)&g_T0p, g_Tx0);
    cudaGetSymbolAddress((void**)&g_T1p, g_Tx1);
    cudaGetSymbolAddress((void**)&g_T2p, g_Tx2);
    cudaGetSymbolAddress((void**)&g_xTp, g_xTAt);
    cudaGetSymbolAddress((void**)&spT_h_p, g_spT_h);
    cudaGetSymbolAddress((void**)&spT_l_p, g_spT_l);
    cudaGetSymbolAddress((void**)&lap_h_p, g_lap_h);
    cudaGetSymbolAddress((void**)&lap_l_p, g_lap_l);
    cudaGetSymbolAddress((void**)&bT_h_p,  g_bT_h);
    cudaGetSymbolAddress((void**)&bT_l_p,  g_bT_l);

    k_u2u3<<<(NN+255)/256, 256>>>(U2, U3);
    k_tred<<<BB*TT, 256>>>(x, U1);
    k_E<<<1, 256>>>(Ve, be);
    k_xTAt<<<BB*NN, 256>>>(x, W1, W2, W3);
    k_vs_tiled<<<(NN*NN+255)/256, 256>>>(Vs);
    k_lap_split<<<(NN*NN+255)/256, 256>>>(lap);
    k_sigP<<<dim3(125,125,BB), 256>>>(bs);

    // S = Vs @ sigP'   (big GEMM, bulk-TMA fed)
    gemm_S_mma<<<dim3(32,32,BB), 256, SMEM_REQ_S>>>();

    k_softmax<<<BB*NN, 256>>>();
    k_tsplit<<<dim3(125,8,BB), 256>>>(g_xTp);

    gemm_bsplit<<<dim3(2,32,BB), 256, SMEM_REQ>>>(
        spT_h_p, spT_l_p, (long long)NN*NN, bT_h_p, bT_l_p, (long long)256*NN,
        g_T0p, (const float*)0, (long long)NN*256, 256, 256, 1.f, 0.f);

    k_tsplit<<<dim3(125,8,BB), 256>>>(g_T0p);

    gemm_bsplit<<<dim3(2,32,BB), 256, SMEM_REQ>>>(
        lap_h_p, lap_l_p, 0LL, bT_h_p, bT_l_p, (long long)256*NN,
        g_T1p, (const float*)0, (long long)NN*256, 256, 256, 1.f, 0.f);

    k_tsplit<<<dim3(125,8,BB), 256>>>(g_T1p);

    gemm_bsplit<<<dim3(2,32,BB), 256, SMEM_REQ>>>(
        lap_h_p, lap_l_p, 0LL, bT_h_p, bT_l_p, (long long)256*NN,
        g_T2p, g_T0p, (long long)NN*256, 256, 256, 2.f, -1.f);

    k_final<<<BB*NN, 256>>>(x, cheb, tw, tb);
    k_stats<<<BB, 256>>>();
    k_out<<<(BB*NN*OO+255)/256, 256>>>(lng, lnb, out);
}

// round 11
// speedup vs baseline: 4.0103x; 1.5300x over previous
#include <cuda_runtime.h>
#include <cuda_bf16.h>
#include <cuda_fp16.h>
#include <math.h>
#include <stdint.h>

#define NN 4000
#define BB 4
#define FF 16
#define TT 16
#define OO 16

__device__ float g_u2u3[NN];
__device__ float g_tlhs[BB*TT];
__device__ float g_trhs[BB*TT];
__device__ float g_E[BB*TT*TT];
__device__ float g_xTAt[BB*NN*FF*TT];
__device__ float g_slhs[BB*NN*FF];
__device__ float g_srhs[BB*NN*FF];
// pre-swizzled chunk-tiled fp16 GEMM operands (zero-init => padding stays 0)
// A (Vs-0.5 quantized): [yb 0..31][chunk 0..62][16KB]
__device__ __align__(256) unsigned char g_At[(size_t)32*63*16384];
// B ((sig-0.5) quantized, transposed): [b][xb 0..31][chunk 0..62][16KB]
__device__ __align__(256) unsigned char g_Bt[(size_t)BB*32*63*16384];
__device__ float g_colsum[BB*NN];
__device__ __align__(256) __nv_bfloat16 g_spT_h[(size_t)BB*NN*NN]; // softmaxed S split (A of xSAtt)
__device__ __align__(256) __nv_bfloat16 g_spT_l[(size_t)BB*NN*NN];
__device__ __align__(256) __nv_bfloat16 g_lap_h[(size_t)NN*NN];
__device__ __align__(256) __nv_bfloat16 g_lap_l[(size_t)NN*NN];
__device__ __align__(256) __nv_bfloat16 g_bT_h[(size_t)BB*256*NN];  // transposed B panels
__device__ __align__(256) __nv_bfloat16 g_bT_l[(size_t)BB*256*NN];
__device__ __align__(256) float g_S[(size_t)BB*NN*NN];
__device__ float g_Tx0[BB*NN*FF*TT];
__device__ float g_Tx1[BB*NN*FF*TT];
__device__ float g_Tx2[BB*NN*FF*TT];
__device__ float g_y[BB*NN*OO];
__device__ float g_stats[BB*2];

__device__ __forceinline__ float sigmoidf_(float v){ return 1.f/(1.f+__expf(-v)); }

// ---- ptx helpers ----
__device__ __forceinline__ uint32_t smem_u32(const void* p){
    uint32_t a;
    asm("{ .reg .u64 t; cvta.to.shared.u64 t, %1; cvt.u32.u64 %0, t; }" : "=r"(a) : "l"(p));
    return a;
}
#define SWZ(o) ((uint32_t)(o) ^ ((((uint32_t)(o)) >> 3) & 0x70u))
__device__ __forceinline__ void cpa16(uint32_t dst, const void* src, bool p){
    int sz = p ? 16 : 0;
    asm volatile("cp.async.cg.shared.global [%0], [%1], 16, %2;" :: "r"(dst), "l"(src), "r"(sz) : "memory");
}
__device__ __forceinline__ void cpa_commit(){ asm volatile("cp.async.commit_group;" ::: "memory"); }
__device__ __forceinline__ void ldsm4(uint32_t* r, uint32_t addr){
    asm volatile("ldmatrix.sync.aligned.m8n8.x4.shared.b16 {%0,%1,%2,%3}, [%4];"
        : "=r"(r[0]),"=r"(r[1]),"=r"(r[2]),"=r"(r[3]) : "r"(addr));
}
__device__ __forceinline__ void ldsm2(uint32_t* r, uint32_t addr){
    asm volatile("ldmatrix.sync.aligned.m8n8.x2.shared.b16 {%0,%1}, [%2];"
        : "=r"(r[0]),"=r"(r[1]) : "r"(addr));
}
__device__ __forceinline__ void mma16816(float* c, const uint32_t* a, const uint32_t* b){
    asm volatile("mma.sync.aligned.m16n8k16.row.col.f32.bf16.bf16.f32 "
        "{%0,%1,%2,%3}, {%4,%5,%6,%7}, {%8,%9}, {%0,%1,%2,%3};"
        : "+f"(c[0]),"+f"(c[1]),"+f"(c[2]),"+f"(c[3])
        : "r"(a[0]),"r"(a[1]),"r"(a[2]),"r"(a[3]), "r"(b[0]),"r"(b[1]));
}
__device__ __forceinline__ void mma16816h(float* c, const uint32_t* a, const uint32_t* b){
    asm volatile("mma.sync.aligned.m16n8k16.row.col.f32.f16.f16.f32 "
        "{%0,%1,%2,%3}, {%4,%5,%6,%7}, {%8,%9}, {%0,%1,%2,%3};"
        : "+f"(c[0]),"+f"(c[1]),"+f"(c[2]),"+f"(c[3])
        : "r"(a[0]),"r"(a[1]),"r"(a[2]),"r"(a[3]), "r"(b[0]),"r"(b[1]));
}
__device__ __forceinline__ void mbar_init(uint32_t a, uint32_t cnt){
    asm volatile("mbarrier.init.shared.b64 [%0], %1;" :: "r"(a), "r"(cnt) : "memory");
}
__device__ __forceinline__ void mbar_expect_tx(uint32_t a, uint32_t bytes){
    asm volatile("mbarrier.arrive.expect_tx.shared.b64 _, [%0], %1;" :: "r"(a), "r"(bytes) : "memory");
}
__device__ __forceinline__ void mbar_wait(uint32_t a, uint32_t ph){
    uint32_t done;
    asm volatile("{\n\t.reg .pred p;\n\t"
        "mbarrier.try_wait.parity.acquire.cta.shared::cta.b64 p, [%1], %2;\n\t"
        "selp.b32 %0, 1, 0, p;\n\t}" : "=r"(done) : "r"(a), "r"(ph) : "memory");
    if (!done){
        asm volatile("{\n\t.reg .pred P1;\n\t"
            "WL%=:\n\t"
            "mbarrier.try_wait.parity.acquire.cta.shared::cta.b64 P1, [%0], %1, 0x989680;\n\t"
            "@P1 bra.uni WD%=;\n\t"
            "bra.uni WL%=;\n\t"
            "WD%=:\n\t}" :: "r"(a), "r"(ph) : "memory");
    }
}
__device__ __forceinline__ void tma_bulk_g2s(uint32_t dst, const void* src, uint32_t bytes, uint32_t mbar){
    asm volatile("cp.async.bulk.shared::cluster.global.mbarrier::complete_tx::bytes [%0], [%1], %2, [%3];"
        :: "r"(dst), "l"(src), "r"(bytes), "r"(mbar) : "memory");
}
// exact 11-bit fixed-point quantization to fp16 (values in [-0.5,0.5])
__device__ __forceinline__ __half q2048(float v){
    int q = __float2int_rn(v*2048.f);
    return __float2half_rn((float)q * (1.f/2048.f));
}

// ---- small kernels ----
__global__ void k_u2u3(const float* __restrict__ U2, const float* __restrict__ U3){
    int n = blockIdx.x*blockDim.x + threadIdx.x;
    if (n < NN){
        float s = 0.f;
        #pragma unroll
        for (int g=0; g<FF; g++) s += U2[g*NN+n]*U3[g];
        g_u2u3[n] = s;
    }
}
__global__ void k_tred(const float* __restrict__ x, const float* __restrict__ U1){
    int b = blockIdx.x >> 4, t = blockIdx.x & 15;
    int tid = threadIdx.x;
    float s1 = 0.f, s2 = 0.f;
    for (int i = tid; i < NN*FF; i += 256){
        int n = i >> 4, f = i & 15;
        float v = x[((size_t)(b*NN+n)*FF+f)*TT + t];
        s1 += v*U1[n]; s2 += v*g_u2u3[n];
    }
    __shared__ float r1[256], r2[256];
    r1[tid]=s1; r2[tid]=s2; __syncthreads();
    for (int o=128; o>0; o>>=1){
        if (tid<o){ r1[tid]+=r1[tid+o]; r2[tid]+=r2[tid+o]; }
        __syncthreads();
    }
    if (tid==0){ g_tlhs[b*TT+t]=r1[0]; g_trhs[b*TT+t]=r2[0]; }
}
__global__ void k_E(const float* __restrict__ Ve, const float* __restrict__ be){
    __shared__ float tl[BB*TT], tr[BB*TT], sVe[TT*TT], sbe[TT*TT], Eb[BB*TT*TT];
    int tid = threadIdx.x;
    if (tid < BB*TT){ tl[tid]=g_tlhs[tid]; tr[tid]=g_trhs[tid]; }
    if (tid < TT*TT){ sVe[tid]=Ve[tid]; sbe[tid]=be[tid]; }
    __syncthreads();
    for (int idx = tid; idx < BB*TT*TT; idx += 256){
        int b = idx>>8, t = (idx>>4)&15, r = idx&15;
        float s = 0.f;
        #pragma unroll
        for (int ss=0; ss<TT; ss++)
            s += sVe[t*TT+ss]*(1.f/(1.f+expf(-(tl[b*TT+ss]*tr[b*TT+r] + sbe[ss*TT+r]))));
        Eb[idx] = s;
    }
    __syncthreads();
    if (tid < BB*TT){
        int base = tid*TT;
        float m = -1e30f;
        for (int r=0;r<TT;r++) m = fmaxf(m, Eb[base+r]);
        float e[TT]; float sum = 0.f;
        for (int r=0;r<TT;r++){ e[r]=expf(Eb[base+r]-m); sum+=e[r]; }
        float inv = 1.f/sum;
        for (int r=0;r<TT;r++) g_E[base+r] = e[r]*inv;
    }
}
__global__ void k_xTAt(const float* __restrict__ x, const float* __restrict__ W1,
                       const float* __restrict__ W2, const float* __restrict__ W3){
    int bn = blockIdx.x;
    int b = bn / NN;
    int tid = threadIdx.x;
    __shared__ float xs[256], Es[256], sr0[16];
    xs[tid] = x[(size_t)bn*256 + tid];
    Es[tid] = g_E[b*256 + tid];
    __syncthreads();
    int f = tid >> 4, t = tid & 15;
    float s = 0.f;
    #pragma unroll
    for (int ss=0; ss<TT; ss++) s += Es[t*16+ss]*xs[f*16+ss];
    g_xTAt[(size_t)bn*256 + tid] = s;
    if (tid < 16){
        float a=0.f, c=0.f;
        #pragma unroll
        for (int t2=0;t2<16;t2++){ float v = xs[tid*16+t2]; a += v*W1[t2]; c += v*W3[t2]; }
        g_slhs[bn*16+tid] = a;
        sr0[tid] = c;
    }
    __syncthreads();
    if (tid < 16){
        float g = 0.f;
        #pragma unroll
        for (int kk=0;kk<16;kk++) g += W2[tid*16+kk]*sr0[kk];
        g_srhs[bn*16+tid] = g;
    }
}
// quantize (Vs-0.5) to fp16 k/2048 grid, tiled+swizzled GEMM layout
__global__ void k_vs_tiled(const float* __restrict__ Vs){
    size_t i = (size_t)blockIdx.x*256 + threadIdx.x;
    if (i < (size_t)NN*NN){
        int n = (int)(i / NN), m = (int)(i % NN);
        __half h = q2048(Vs[i] - 0.5f);
        int yb = n>>7, r = n&127, ch = m>>6, sg = m&63;
        size_t tb = ((size_t)yb*63 + ch)*16384;
        uint32_t off = SWZ((uint32_t)(r*128 + sg*2));
        *(__half*)(g_At + tb + off) = h;
    }
}
__global__ void k_lap_split(const float* __restrict__ lap){
    size_t i = (size_t)blockIdx.x*256 + threadIdx.x;
    if (i < (size_t)NN*NN){
        float v = lap[i];
        __nv_bfloat16 h = __float2bfloat16(v);
        g_lap_h[i] = h;
        g_lap_l[i] = __float2bfloat16(v - __bfloat162float(h));
    }
}
__global__ void k_zero_cs(){
    int i = blockIdx.x*256 + threadIdx.x;
    if (i < BB*NN) g_colsum[i] = 0.f;
}
// transpose-split: X [b][NN][256] fp32 -> XT [b][256][NN] bf16 h/l
__global__ void k_tsplit(const float* __restrict__ X){
    int b = blockIdx.z;
    int m0 = blockIdx.x*32, c0 = blockIdx.y*32;
    int tx = threadIdx.x & 31, ty = threadIdx.x >> 5;
    __shared__ float t[32][33];
    const float* Xb = X + (size_t)b*NN*256;
    #pragma unroll
    for (int i=0;i<4;i++){
        int row = ty + i*8;
        t[row][tx] = Xb[(size_t)(m0+row)*256 + c0 + tx];
    }
    __syncthreads();
    __nv_bfloat16* Th = g_bT_h + (size_t)b*256*NN;
    __nv_bfloat16* Tl = g_bT_l + (size_t)b*256*NN;
    #pragma unroll
    for (int i=0;i<4;i++){
        int row = ty + i*8;
        float v = t[tx][row];
        __nv_bfloat16 h = __float2bfloat16(v);
        size_t o = (size_t)(c0+row)*NN + m0 + tx;
        Th[o] = h;
        Tl[o] = __float2bfloat16(v - __bfloat162float(h));
    }
}
// sigmoid(prod+bs) - 0.5, quantized fp16, tiled layout [b][xb][ch], + colsum over m
__global__ void k_sigP(const float* __restrict__ bs){
    int b = blockIdx.z;
    int m0 = blockIdx.y*32, k0 = blockIdx.x*32;
    int tid = threadIdx.x, lane = tid&31;
    __shared__ float Lm[32][17], Rk[32][17], sbs[32][33];
    for (int i = tid; i < 512; i += 256){
        int r = i>>4, c = i&15;
        Lm[r][c] = g_slhs[(b*NN + m0 + r)*16 + c];
        Rk[r][c] = g_srhs[(b*NN + k0 + r)*16 + c];
    }
    for (int i = tid; i < 1024; i += 256){
        int mi = i>>5, ki = i&31;
        sbs[mi][ki] = bs[(size_t)(m0+mi)*NN + k0 + ki];
    }
    __syncthreads();
    for (int e = tid; e < 1024; e += 256){
        int ki = e>>5, mi = e&31;   // mi == lane
        float d = sbs[mi][ki];
        #pragma unroll
        for (int f=0; f<16; f++) d += Lm[mi][f]*Rk[ki][f];
        float s = sigmoidf_(d) - 0.5f;
        __half h = q2048(s);
        int kg = k0 + ki;       // output-col of S (tile row)
        int mg = m0 + mi;       // contraction index
        int xb = kg>>7, r = kg&127, ch = mg>>6, sg = mg&63;
        size_t tb = ((size_t)(b*32 + xb)*63 + ch)*16384;
        uint32_t off = SWZ((uint32_t)(r*128 + sg*2));
        *(__half*)(g_Bt + tb + off) = h;
        // colsum over mi (warp lanes) for this ki
        float cs = s;
        #pragma unroll
        for (int off2=16; off2>0; off2>>=1) cs += __shfl_down_sync(0xFFFFFFFFu, cs, off2);
        if (lane==0) atomicAdd(&g_colsum[b*NN + kg], cs);
    }
}

#define KCHUNK 64
#define NCHUNK 63
#define NSTAGE 3
#define STG_BYTES 65536
#define OFF_AH 0
#define OFF_AL 16384
#define OFF_BH 32768
#define OFF_BL 49152
#define SMEM_REQ (NSTAGE*STG_BYTES + 1024)
// fp16 single-pass gemm_S: 32KB stages
#define S_STG 32768
#define SMEM_REQ_S (NSTAGE*S_STG + 2048)

// ---- big GEMM: single-pass fp16, bulk-TMA fed, + colsum correction ----
__global__ void __launch_bounds__(256,1) gemm_S_mma(){
    extern __shared__ char dsm[];
    uint32_t sb = (smem_u32(dsm) + 1023u) & ~1023u;
    uint32_t mb = sb + NSTAGE*S_STG;   // 3 mbarriers
    int tid = threadIdx.x, lane = tid&31, wid = tid>>5;
    int b = blockIdx.z;
    int yb = blockIdx.y, xb = blockIdx.x;
    int mBase = yb*128, nBase = xb*128;
    int wm = wid>>1, wn = wid&1;

    const unsigned char* Asrc = g_At + (size_t)yb*63*16384;
    const unsigned char* Bsrc = g_Bt + ((size_t)(b*32 + xb))*63*16384;

    if (tid==0){
        mbar_init(mb,1); mbar_init(mb+8,1); mbar_init(mb+16,1);
    }
    __syncthreads();
    if (tid==0){
        #pragma unroll
        for (int p=0;p<NSTAGE;p++){
            uint32_t bar = mb + p*8;
            mbar_expect_tx(bar, 32768);
            tma_bulk_g2s(sb + p*S_STG,          Asrc + (size_t)p*16384, 16384, bar);
            tma_bulk_g2s(sb + p*S_STG + 16384,  Bsrc + (size_t)p*16384, 16384, bar);
        }
    }

    float acc[2][8][4];
    #pragma unroll
    for (int i=0;i<2;i++)
        #pragma unroll
        for (int j=0;j<8;j++)
            #pragma unroll
            for (int q=0;q<4;q++) acc[i][j][q]=0.f;

    for (int c=0;c<NCHUNK;c++){
        int s = c%NSTAGE;
        mbar_wait(mb + s*8, (uint32_t)((c/NSTAGE)&1));
        uint32_t stg = sb + s*S_STG;
        #pragma unroll
        for (int ks=0;ks<4;ks++){
            uint32_t ah[2][4];
            #pragma unroll
            for (int mt=0;mt<2;mt++){
                int row = wm*32 + mt*16 + (lane&15);
                uint32_t bo = SWZ(row*128 + ks*32 + (lane>>4)*16);
                ldsm4(ah[mt], stg + bo);
            }
            uint32_t bh[8][2];
            #pragma unroll
            for (int nt=0;nt<8;nt++){
                int row = wn*64 + nt*8 + (lane&7);
                uint32_t bo = SWZ(row*128 + ks*32 + ((lane>>3)&1)*16);
                ldsm2(bh[nt], stg + 16384 + bo);
            }
            #pragma unroll
            for (int mt=0;mt<2;mt++)
                #pragma unroll
                for (int nt=0;nt<8;nt++)
                    mma16816h(acc[mt][nt], ah[mt], bh[nt]);
        }
        __syncthreads();
        if (tid==0 && (c+NSTAGE) < NCHUNK){
            int cn = c+NSTAGE;
            uint32_t bar = mb + s*8;
            mbar_expect_tx(bar, 32768);
            tma_bulk_g2s(stg,          Asrc + (size_t)cn*16384, 16384, bar);
            tma_bulk_g2s(stg + 16384,  Bsrc + (size_t)cn*16384, 16384, bar);
        }
    }

    float* C = g_S + (size_t)b*NN*NN;
    const float* CS = g_colsum + b*NN;
    int tig = lane&3, grp = lane>>2;
    #pragma unroll
    for (int mt=0;mt<2;mt++){
        int r0 = mBase + wm*32 + mt*16 + grp;
        int r1 = r0 + 8;
        #pragma unroll
        for (int nt=0;nt<8;nt++){
            int c0 = nBase + wn*64 + nt*8 + tig*2;
            if (c0 < NN){
                bool c1ok = (c0+1) < NN;
                float cs0 = 0.5f*CS[c0];
                float cs1 = c1ok ? 0.5f*CS[c0+1] : 0.f;
                if (r0 < NN){
                    C[(size_t)r0*NN + c0] = acc[mt][nt][0] + cs0;
                    if (c1ok) C[(size_t)r0*NN + c0 + 1] = acc[mt][nt][1] + cs1;
                }
                if (r1 < NN){
                    C[(size_t)r1*NN + c0] = acc[mt][nt][2] + cs0;
                    if (c1ok) C[(size_t)r1*NN + c0 + 1] = acc[mt][nt][3] + cs1;
                }
            }
        }
    }
}

// ---- generic bf16-split tensor GEMM (3-pass), 256 threads, for the small GEMMs ----
__global__ void __launch_bounds__(256,1) gemm_bsplit(
    const __nv_bfloat16* __restrict__ gAh, const __nv_bfloat16* __restrict__ gAl, long long sAb,
    const __nv_bfloat16* __restrict__ gBh, const __nv_bfloat16* __restrict__ gBl, long long sBb,
    float* __restrict__ gC, const float* __restrict__ gD, long long sCb,
    int ldc, int Ncols, float alpha, float beta)
{
    extern __shared__ char dsm[];
    uint32_t sb = (smem_u32(dsm) + 1023u) & ~1023u;
    int tid = threadIdx.x, lane = tid&31, wid = tid>>5;
    int b = blockIdx.z;
    int mBase = blockIdx.y*128, nBase = blockIdx.x*128;
    int wm = wid>>1, wn = wid&1;

    const __nv_bfloat16* Ahp = gAh + (size_t)b*sAb;
    const __nv_bfloat16* Alp = gAl + (size_t)b*sAb;
    const __nv_bfloat16* Bhp = gBh + (size_t)b*sBb;
    const __nv_bfloat16* Blp = gBl + (size_t)b*sBb;

    float acc[2][8][4];
    #pragma unroll
    for (int i=0;i<2;i++)
        #pragma unroll
        for (int j=0;j<8;j++)
            #pragma unroll
            for (int q=0;q<4;q++) acc[i][j][q]=0.f;

    #define ISSUE_STAGE(c_) do{ \
        int st_ = (c_)%NSTAGE; uint32_t stg_ = sb + st_*STG_BYTES; \
        int k0_ = (c_)*KCHUNK; \
        _Pragma("unroll") \
        for (int j_=0;j_<4;j_++){ \
            int op_ = j_*256+tid; int row_ = op_>>3, ch_ = op_&7; \
            int kk_ = k0_ + ch_*8; \
            uint32_t so_ = SWZ(row_*128 + ch_*16); \
            bool va_ = (kk_ < NN) && ((mBase+row_) < NN); \
            size_t ga_ = va_ ? ((size_t)(mBase+row_)*NN + kk_) : 0; \
            cpa16(stg_+OFF_AH+so_, Ahp+ga_, va_); \
            cpa16(stg_+OFF_AL+so_, Alp+ga_, va_); \
            bool vb_ = (kk_ < NN) && ((nBase+row_) < Ncols); \
            size_t gb_ = vb_ ? ((size_t)(nBase+row_)*NN + kk_) : 0; \
            cpa16(stg_+OFF_BH+so_, Bhp+gb_, vb_); \
            cpa16(stg_+OFF_BL+so_, Blp+gb_, vb_); \
        } \
        cpa_commit(); \
    }while(0)

    ISSUE_STAGE(0);
    ISSUE_STAGE(1);
    ISSUE_STAGE(2);

    for (int c=0;c<NCHUNK;c++){
        asm volatile("cp.async.wait_group 2;" ::: "memory");
        __syncthreads();
        uint32_t stg = sb + (c%NSTAGE)*STG_BYTES;
        #pragma unroll
        for (int ks=0;ks<4;ks++){
            uint32_t ah[2][4], al[2][4];
            #pragma unroll
            for (int mt=0;mt<2;mt++){
                int row = wm*32 + mt*16 + (lane&15);
                uint32_t bo = SWZ(row*128 + ks*32 + (lane>>4)*16);
                ldsm4(ah[mt], stg+OFF_AH+bo);
                ldsm4(al[mt], stg+OFF_AL+bo);
            }
            uint32_t bh[8][2], bl[8][2];
            #pragma unroll
            for (int nt=0;nt<8;nt++){
                int row = wn*64 + nt*8 + (lane&7);
                uint32_t bo = SWZ(row*128 + ks*32 + ((lane>>3)&1)*16);
                ldsm2(bh[nt], stg+OFF_BH+bo);
                ldsm2(bl[nt], stg+OFF_BL+bo);
            }
            #pragma unroll
            for (int mt=0;mt<2;mt++)
                #pragma unroll
                for (int nt=0;nt<8;nt++){
                    mma16816(acc[mt][nt], ah[mt], bh[nt]);
                    mma16816(acc[mt][nt], ah[mt], bl[nt]);
                    mma16816(acc[mt][nt], al[mt], bh[nt]);
                }
        }
        __syncthreads();
        if (c+NSTAGE < NCHUNK){ ISSUE_STAGE(c+NSTAGE); }
        else { cpa_commit(); }
    }
    #undef ISSUE_STAGE

    float* C = gC + (size_t)b*sCb;
    const float* D = gD ? gD + (size_t)b*sCb : (const float*)0;
    int tig = lane&3, grp = lane>>2;
    #pragma unroll
    for (int mt=0;mt<2;mt++){
        int r0 = mBase + wm*32 + mt*16 + grp;
        int r1 = r0 + 8;
        #pragma unroll
        for (int nt=0;nt<8;nt++){
            int c0 = nBase + wn*64 + nt*8 + tig*2;
            if (c0 < Ncols){
                bool c1ok = (c0+1) < Ncols;
                if (r0 < NN){
                    float v0 = alpha*acc[mt][nt][0];
                    if (D) v0 += beta*D[(size_t)r0*ldc + c0];
                    C[(size_t)r0*ldc + c0] = v0;
                    if (c1ok){
                        float v1 = alpha*acc[mt][nt][1];
                        if (D) v1 += beta*D[(size_t)r0*ldc + c0 + 1];
                        C[(size_t)r0*ldc + c0 + 1] = v1;
                    }
                }
                if (r1 < NN){
                    float v2 = alpha*acc[mt][nt][2];
                    if (D) v2 += beta*D[(size_t)r1*ldc + c0];
                    C[(size_t)r1*ldc + c0] = v2;
                    if (c1ok){
                        float v3 = alpha*acc[mt][nt][3];
                        if (D) v3 += beta*D[(size_t)r1*ldc + c0 + 1];
                        C[(size_t)r1*ldc + c0 + 1] = v3;
                    }
                }
            }
        }
    }
}

// softmax over last dim of S; writes bf16 h/l split (A operand of xSAtt)
__global__ void k_softmax(){
    __shared__ float row[NN];
    __shared__ float red[256];
    int tid = threadIdx.x;
    size_t base = (size_t)blockIdx.x * NN;
    float m = -1e30f;
    for (int i = tid; i < NN; i += 256){ float v = g_S[base+i]; row[i]=v; m = fmaxf(m,v); }
    red[tid]=m; __syncthreads();
    for (int o=128;o>0;o>>=1){ if (tid<o) red[tid]=fmaxf(red[tid],red[tid+o]); __syncthreads(); }
    m = red[0]; __syncthreads();
    float s = 0.f;
    for (int i = tid; i < NN; i += 256){ float e = __expf(row[i]-m); row[i]=e; s += e; }
    red[tid]=s; __syncthreads();
    for (int o=128;o>0;o>>=1){ if (tid<o) red[tid]+=red[tid+o]; __syncthreads(); }
    float inv = 1.f/red[0];
    for (int i = tid; i < NN; i += 256){
        float p = row[i]*inv;
        __nv_bfloat16 h = __float2bfloat16(p);
        g_spT_h[base+i] = h;
        g_spT_l[base+i] = __float2bfloat16(p - __bfloat162float(h));
    }
}

__global__ void k_final(const float* __restrict__ x, const float* __restrict__ cheb,
                        const float* __restrict__ tw, const float* __restrict__ tb){
    int bn = blockIdx.x;
    int tid = threadIdx.x;
    __shared__ float xs[256], t0[256], t1[256], t2[256], ts0[16], ts1[16], ts2[16];
    size_t rb = (size_t)bn*256;
    xs[tid]=x[rb+tid]; t0[tid]=g_Tx0[rb+tid]; t1[tid]=g_Tx1[rb+tid]; t2[tid]=g_Tx2[rb+tid];
    __syncthreads();
    if (tid < 48){
        int kk = tid>>4, f = tid&15;
        const float* src = (kk==0) ? t0 : ((kk==1) ? t1 : t2);
        float s = 0.f;
        #pragma unroll
        for (int t=0;t<16;t++) s += src[f*16+t];
        float* dst = (kk==0) ? ts0 : ((kk==1) ? ts1 : ts2);
        dst[f] = s;
    }
    __syncthreads();
    if (tid < 16){
        int o = tid;
        float tm = 0.f;
        #pragma unroll
        for (int c=0;c<16;c++)
            #pragma unroll
            for (int t=0;t<16;t++) tm += xs[c*16+t]*tw[(o*16+c)*16+t];
        float sp = 0.f;
        #pragma unroll
        for (int f=0;f<16;f++)
            sp += ts0[f]*cheb[f*16+o] + ts1[f]*cheb[256+f*16+o] + ts2[f]*cheb[512+f*16+o];
        g_y[bn*16+o] = sp*(1.f/16.f) + tm + tb[o] + xs[o*16+15];
    }
}

__global__ void k_stats(){
    int b = blockIdx.x, tid = threadIdx.x;
    double s = 0.0, ss = 0.0;
    for (int i = tid; i < NN*OO; i += 256){
        float v = g_y[b*NN*OO + i];
        s += (double)v; ss += (double)v*(double)v;
    }
    __shared__ double rs[256], rq[256];
    rs[tid]=s; rq[tid]=ss; __syncthreads();
    for (int o=128;o>0;o>>=1){ if (tid<o){ rs[tid]+=rs[tid+o]; rq[tid]+=rq[tid+o]; } __syncthreads(); }
    if (tid==0){
        double mean = rs[0]/(double)(NN*OO);
        double var  = rq[0]/(double)(NN*OO) - mean*mean;
        g_stats[b*2]   = (float)mean;
        g_stats[b*2+1] = (float)(1.0/sqrt(var + 1e-5));
    }
}
__global__ void k_out(const float* __restrict__ lng, const float* __restrict__ lnb,
                      float* __restrict__ out){
    int i = blockIdx.x*256 + threadIdx.x;
    if (i < BB*NN*OO){
        int b  = i / (NN*OO);
        int no = i % (NN*OO);
        float v = (g_y[i]-g_stats[b*2])*g_stats[b*2+1]*lng[no] + lnb[no];
        out[i] = fmaxf(v, 0.f);
    }
}

extern "C" void kernel_launch(void* const* d_in, const int* in_sizes, int n_in,
                              void* d_out, int out_size){
    const float* x    = (const float*)d_in[0];
    const float* lap  = (const float*)d_in[1];
    const float* W1   = (const float*)d_in[2];
    const float* W2   = (const float*)d_in[3];
    const float* W3   = (const float*)d_in[4];
    const float* bs   = (const float*)d_in[5];
    const float* Vs   = (const float*)d_in[6];
    const float* U1   = (const float*)d_in[7];
    const float* U2   = (const float*)d_in[8];
    const float* U3   = (const float*)d_in[9];
    const float* be   = (const float*)d_in[10];
    const float* Ve   = (const float*)d_in[11];
    const float* cheb = (const float*)d_in[12];
    const float* tw   = (const float*)d_in[13];
    const float* tb   = (const float*)d_in[14];
    const float* lng  = (const float*)d_in[15];
    const float* lnb  = (const float*)d_in[16];
    float* out = (float*)d_out;

    static int smem_set = 0;
    if (!smem_set){
        cudaFuncSetAttribute(gemm_bsplit, cudaFuncAttributeMaxDynamicSharedMemorySize, SMEM_REQ);
        cudaFuncSetAttribute(gemm_S_mma,  cudaFuncAttributeMaxDynamicSharedMemorySize, SMEM_REQ_S);
        smem_set = 1;
    }

    float *g_T0p, *g_T1p, *g_T2p, *g_xTp;
    __nv_bfloat16 *spT_h_p, *spT_l_p, *lap_h_p, *lap_l_p, *bT_h_p, *bT_l_p;
    cudaGetSymbolAddress((void**)&g_T0p, g_Tx0);
    cudaGetSymbolAddress((void**)&g_T1p, g_Tx1);
    cudaGetSymbolAddress((void**)&g_T2p, g_Tx2);
    cudaGetSymbolAddress((void**)&g_xTp, g_xTAt);
    cudaGetSymbolAddress((void**)&spT_h_p, g_spT_h);
    cudaGetSymbolAddress((void**)&spT_l_p, g_spT_l);
    cudaGetSymbolAddress((void**)&lap_h_p, g_lap_h);
    cudaGetSymbolAddress((void**)&lap_l_p, g_lap_l);
    cudaGetSymbolAddress((void**)&bT_h_p,  g_bT_h);
    cudaGetSymbolAddress((void**)&bT_l_p,  g_bT_l);

    k_u2u3<<<(NN+255)/256, 256>>>(U2, U3);
    k_tred<<<BB*TT, 256>>>(x, U1);
    k_E<<<1, 256>>>(Ve, be);
    k_xTAt<<<BB*NN, 256>>>(x, W1, W2, W3);
    k_vs_tiled<<<(NN*NN+255)/256, 256>>>(Vs);
    k_lap_split<<<(NN*NN+255)/256, 256>>>(lap);
    k_zero_cs<<<(BB*NN+255)/256, 256>>>();
    k_sigP<<<dim3(125,125,BB), 256>>>(bs);

    // S = (Vs-.5)@(sig-.5) + 0.5*colsum   (single-pass fp16, bulk-TMA fed)
    gemm_S_mma<<<dim3(32,32,BB), 256, SMEM_REQ_S>>>();

    k_softmax<<<BB*NN, 256>>>();
    k_tsplit<<<dim3(125,8,BB), 256>>>(g_xTp);

    gemm_bsplit<<<dim3(2,32,BB), 256, SMEM_REQ>>>(
        spT_h_p, spT_l_p, (long long)NN*NN, bT_h_p, bT_l_p, (long long)256*NN,
        g_T0p, (const float*)0, (long long)NN*256, 256, 256, 1.f, 0.f);

    k_tsplit<<<dim3(125,8,BB), 256>>>(g_T0p);

    gemm_bsplit<<<dim3(2,32,BB), 256, SMEM_REQ>>>(
        lap_h_p, lap_l_p, 0LL, bT_h_p, bT_l_p, (long long)256*NN,
        g_T1p, (const float*)0, (long long)NN*256, 256, 256, 1.f, 0.f);

    k_tsplit<<<dim3(125,8,BB), 256>>>(g_T1p);

    gemm_bsplit<<<dim3(2,32,BB), 256, SMEM_REQ>>>(
        lap_h_p, lap_l_p, 0LL, bT_h_p, bT_l_p, (long long)256*NN,
        g_T2p, g_T0p, (long long)NN*256, 256, 256, 2.f, -1.f);

    k_final<<<BB*NN, 256>>>(x, cheb, tw, tb);
    k_stats<<<BB, 256>>>();
    k_out<<<(BB*NN*OO+255)/256, 256>>>(lng, lnb, out);
}

// round 12
// speedup vs baseline: 4.5086x; 1.1243x over previous
#include <cuda_runtime.h>
#include <cuda_bf16.h>
#include <cuda_fp16.h>
#include <math.h>
#include <stdint.h>

#define NN 4000
#define BB 4
#define FF 16
#define TT 16
#define OO 16

__device__ float g_u2u3[NN];
__device__ float g_tlhs[BB*TT];
__device__ float g_trhs[BB*TT];
__device__ float g_E[BB*TT*TT];
__device__ float g_xTAt[BB*NN*FF*TT];
__device__ float g_slhs[BB*NN*FF];
__device__ float g_srhs[BB*NN*FF];
// pre-swizzled chunk-tiled fp16 GEMM operands (zero-init => padding stays 0)
__device__ __align__(256) unsigned char g_At[(size_t)32*63*16384];
__device__ __align__(256) unsigned char g_Bt[(size_t)BB*32*63*16384];
__device__ float g_colsum[BB*NN];
__device__ __align__(256) __nv_bfloat16 g_spT_h[(size_t)BB*NN*NN]; // softmaxed S split (A of xSAtt)
__device__ __align__(256) __nv_bfloat16 g_spT_l[(size_t)BB*NN*NN];
__device__ __align__(256) __nv_bfloat16 g_lap_h[(size_t)NN*NN];
__device__ __align__(256) __nv_bfloat16 g_lap_l[(size_t)NN*NN];
__device__ __align__(256) __nv_bfloat16 g_bT_h[(size_t)BB*256*NN];  // transposed B panels
__device__ __align__(256) __nv_bfloat16 g_bT_l[(size_t)BB*256*NN];
__device__ __align__(256) float g_S[(size_t)BB*NN*NN];
__device__ float g_Tx0[BB*NN*FF*TT];
__device__ float g_Tx1[BB*NN*FF*TT];
__device__ float g_Tx2[BB*NN*FF*TT];
__device__ float g_y[BB*NN*OO];
__device__ float g_stats[BB*2];

__device__ __forceinline__ float tanh_ap(float x){
    float y; asm("tanh.approx.f32 %0, %1;" : "=f"(y) : "f"(x)); return y;
}

// ---- ptx helpers ----
__device__ __forceinline__ uint32_t smem_u32(const void* p){
    uint32_t a;
    asm("{ .reg .u64 t; cvta.to.shared.u64 t, %1; cvt.u32.u64 %0, t; }" : "=r"(a) : "l"(p));
    return a;
}
#define SWZ(o) ((uint32_t)(o) ^ ((((uint32_t)(o)) >> 3) & 0x70u))
__device__ __forceinline__ void cpa16(uint32_t dst, const void* src, bool p){
    int sz = p ? 16 : 0;
    asm volatile("cp.async.cg.shared.global [%0], [%1], 16, %2;" :: "r"(dst), "l"(src), "r"(sz) : "memory");
}
__device__ __forceinline__ void cpa_commit(){ asm volatile("cp.async.commit_group;" ::: "memory"); }
__device__ __forceinline__ void ldsm4(uint32_t* r, uint32_t addr){
    asm volatile("ldmatrix.sync.aligned.m8n8.x4.shared.b16 {%0,%1,%2,%3}, [%4];"
        : "=r"(r[0]),"=r"(r[1]),"=r"(r[2]),"=r"(r[3]) : "r"(addr));
}
__device__ __forceinline__ void ldsm2(uint32_t* r, uint32_t addr){
    asm volatile("ldmatrix.sync.aligned.m8n8.x2.shared.b16 {%0,%1}, [%2];"
        : "=r"(r[0]),"=r"(r[1]) : "r"(addr));
}
__device__ __forceinline__ void mma16816(float* c, const uint32_t* a, const uint32_t* b){
    asm volatile("mma.sync.aligned.m16n8k16.row.col.f32.bf16.bf16.f32 "
        "{%0,%1,%2,%3}, {%4,%5,%6,%7}, {%8,%9}, {%0,%1,%2,%3};"
        : "+f"(c[0]),"+f"(c[1]),"+f"(c[2]),"+f"(c[3])
        : "r"(a[0]),"r"(a[1]),"r"(a[2]),"r"(a[3]), "r"(b[0]),"r"(b[1]));
}
__device__ __forceinline__ void mma16816h(float* c, const uint32_t* a, const uint32_t* b){
    asm volatile("mma.sync.aligned.m16n8k16.row.col.f32.f16.f16.f32 "
        "{%0,%1,%2,%3}, {%4,%5,%6,%7}, {%8,%9}, {%0,%1,%2,%3};"
        : "+f"(c[0]),"+f"(c[1]),"+f"(c[2]),"+f"(c[3])
        : "r"(a[0]),"r"(a[1]),"r"(a[2]),"r"(a[3]), "r"(b[0]),"r"(b[1]));
}
__device__ __forceinline__ void mbar_init(uint32_t a, uint32_t cnt){
    asm volatile("mbarrier.init.shared.b64 [%0], %1;" :: "r"(a), "r"(cnt) : "memory");
}
__device__ __forceinline__ void mbar_expect_tx(uint32_t a, uint32_t bytes){
    asm volatile("mbarrier.arrive.expect_tx.shared.b64 _, [%0], %1;" :: "r"(a), "r"(bytes) : "memory");
}
__device__ __forceinline__ void mbar_wait(uint32_t a, uint32_t ph){
    uint32_t done;
    asm volatile("{\n\t.reg .pred p;\n\t"
        "mbarrier.try_wait.parity.acquire.cta.shared::cta.b64 p, [%1], %2;\n\t"
        "selp.b32 %0, 1, 0, p;\n\t}" : "=r"(done) : "r"(a), "r"(ph) : "memory");
    if (!done){
        asm volatile("{\n\t.reg .pred P1;\n\t"
            "WL%=:\n\t"
            "mbarrier.try_wait.parity.acquire.cta.shared::cta.b64 P1, [%0], %1, 0x989680;\n\t"
            "@P1 bra.uni WD%=;\n\t"
            "bra.uni WL%=;\n\t"
            "WD%=:\n\t}" :: "r"(a), "r"(ph) : "memory");
    }
}
__device__ __forceinline__ void tma_bulk_g2s(uint32_t dst, const void* src, uint32_t bytes, uint32_t mbar){
    asm volatile("cp.async.bulk.shared::cluster.global.mbarrier::complete_tx::bytes [%0], [%1], %2, [%3];"
        :: "r"(dst), "l"(src), "r"(bytes), "r"(mbar) : "memory");
}
// exact 11-bit fixed-point quantization to fp16 (values in [-0.5,0.5])
__device__ __forceinline__ __half q2048(float v){
    int q = __float2int_rn(v*2048.f);
    return __float2half_rn((float)q * (1.f/2048.f));
}

// ---- small kernels ----
__global__ void k_u2u3(const float* __restrict__ U2, const float* __restrict__ U3){
    int n = blockIdx.x*blockDim.x + threadIdx.x;
    if (n < NN){
        float s = 0.f;
        #pragma unroll
        for (int g=0; g<FF; g++) s += U2[g*NN+n]*U3[g];
        g_u2u3[n] = s;
    }
}
__global__ void k_tred(const float* __restrict__ x, const float* __restrict__ U1){
    int b = blockIdx.x >> 4, t = blockIdx.x & 15;
    int tid = threadIdx.x;
    float s1 = 0.f, s2 = 0.f;
    for (int i = tid; i < NN*FF; i += 256){
        int n = i >> 4, f = i & 15;
        float v = x[((size_t)(b*NN+n)*FF+f)*TT + t];
        s1 += v*U1[n]; s2 += v*g_u2u3[n];
    }
    __shared__ float r1[256], r2[256];
    r1[tid]=s1; r2[tid]=s2; __syncthreads();
    for (int o=128; o>0; o>>=1){
        if (tid<o){ r1[tid]+=r1[tid+o]; r2[tid]+=r2[tid+o]; }
        __syncthreads();
    }
    if (tid==0){ g_tlhs[b*TT+t]=r1[0]; g_trhs[b*TT+t]=r2[0]; }
}
__global__ void k_E(const float* __restrict__ Ve, const float* __restrict__ be){
    __shared__ float tl[BB*TT], tr[BB*TT], sVe[TT*TT], sbe[TT*TT], Eb[BB*TT*TT];
    int tid = threadIdx.x;
    if (tid < BB*TT){ tl[tid]=g_tlhs[tid]; tr[tid]=g_trhs[tid]; }
    if (tid < TT*TT){ sVe[tid]=Ve[tid]; sbe[tid]=be[tid]; }
    __syncthreads();
    for (int idx = tid; idx < BB*TT*TT; idx += 256){
        int b = idx>>8, t = (idx>>4)&15, r = idx&15;
        float s = 0.f;
        #pragma unroll
        for (int ss=0; ss<TT; ss++)
            s += sVe[t*TT+ss]*(1.f/(1.f+expf(-(tl[b*TT+ss]*tr[b*TT+r] + sbe[ss*TT+r]))));
        Eb[idx] = s;
    }
    __syncthreads();
    if (tid < BB*TT){
        int base = tid*TT;
        float m = -1e30f;
        for (int r=0;r<TT;r++) m = fmaxf(m, Eb[base+r]);
        float e[TT]; float sum = 0.f;
        for (int r=0;r<TT;r++){ e[r]=expf(Eb[base+r]-m); sum+=e[r]; }
        float inv = 1.f/sum;
        for (int r=0;r<TT;r++) g_E[base+r] = e[r]*inv;
    }
}
__global__ void k_xTAt(const float* __restrict__ x, const float* __restrict__ W1,
                       const float* __restrict__ W2, const float* __restrict__ W3){
    int bn = blockIdx.x;
    int b = bn / NN;
    int tid = threadIdx.x;
    __shared__ float xs[256], Es[256], sr0[16];
    xs[tid] = x[(size_t)bn*256 + tid];
    Es[tid] = g_E[b*256 + tid];
    __syncthreads();
    int f = tid >> 4, t = tid & 15;
    float s = 0.f;
    #pragma unroll
    for (int ss=0; ss<TT; ss++) s += Es[t*16+ss]*xs[f*16+ss];
    g_xTAt[(size_t)bn*256 + tid] = s;
    if (tid < 16){
        float a=0.f, c=0.f;
        #pragma unroll
        for (int t2=0;t2<16;t2++){ float v = xs[tid*16+t2]; a += v*W1[t2]; c += v*W3[t2]; }
        g_slhs[bn*16+tid] = a;
        sr0[tid] = c;
    }
    __syncthreads();
    if (tid < 16){
        float g = 0.f;
        #pragma unroll
        for (int kk=0;kk<16;kk++) g += W2[tid*16+kk]*sr0[kk];
        g_srhs[bn*16+tid] = g;
    }
}
// quantize (Vs-0.5) to fp16 k/2048 grid, tiled+swizzled GEMM layout
__global__ void k_vs_tiled(const float* __restrict__ Vs){
    size_t i = (size_t)blockIdx.x*256 + threadIdx.x;
    if (i < (size_t)NN*NN){
        int n = (int)(i / NN), m = (int)(i % NN);
        __half h = q2048(Vs[i] - 0.5f);
        int yb = n>>7, r = n&127, ch = m>>6, sg = m&63;
        size_t tb = ((size_t)yb*63 + ch)*16384;
        uint32_t off = SWZ((uint32_t)(r*128 + sg*2));
        *(__half*)(g_At + tb + off) = h;
    }
}
__global__ void k_lap_split(const float* __restrict__ lap){
    size_t i = (size_t)blockIdx.x*256 + threadIdx.x;
    if (i < (size_t)NN*NN){
        float v = lap[i];
        __nv_bfloat16 h = __float2bfloat16(v);
        g_lap_h[i] = h;
        g_lap_l[i] = __float2bfloat16(v - __bfloat162float(h));
    }
}
__global__ void k_zero_cs(){
    int i = blockIdx.x*256 + threadIdx.x;
    if (i < BB*NN) g_colsum[i] = 0.f;
}
// transpose-split: X [b][NN][256] fp32 -> XT [b][256][NN] bf16 h/l
__global__ void k_tsplit(const float* __restrict__ X){
    int b = blockIdx.z;
    int m0 = blockIdx.x*32, c0 = blockIdx.y*32;
    int tx = threadIdx.x & 31, ty = threadIdx.x >> 5;
    __shared__ float t[32][33];
    const float* Xb = X + (size_t)b*NN*256;
    #pragma unroll
    for (int i=0;i<4;i++){
        int row = ty + i*8;
        t[row][tx] = Xb[(size_t)(m0+row)*256 + c0 + tx];
    }
    __syncthreads();
    __nv_bfloat16* Th = g_bT_h + (size_t)b*256*NN;
    __nv_bfloat16* Tl = g_bT_l + (size_t)b*256*NN;
    #pragma unroll
    for (int i=0;i<4;i++){
        int row = ty + i*8;
        float v = t[tx][row];
        __nv_bfloat16 h = __float2bfloat16(v);
        size_t o = (size_t)(c0+row)*NN + m0 + tx;
        Th[o] = h;
        Tl[o] = __float2bfloat16(v - __bfloat162float(h));
    }
}
// (sigmoid-0.5) = 0.5*tanh(d/2)  (1 MUFU), quantized fp16, tiled layout, colsum of stored value
__global__ void k_sigP(const float* __restrict__ bs){
    int b = blockIdx.z;
    int m0 = blockIdx.y*32, k0 = blockIdx.x*32;
    int tid = threadIdx.x, lane = tid&31;
    __shared__ float Lm[32][17], Rk[32][17], sbs[32][33];
    for (int i = tid; i < 512; i += 256){
        int r = i>>4, c = i&15;
        Lm[r][c] = g_slhs[(b*NN + m0 + r)*16 + c];
        Rk[r][c] = g_srhs[(b*NN + k0 + r)*16 + c];
    }
    for (int i = tid; i < 1024; i += 256){
        int mi = i>>5, ki = i&31;
        sbs[mi][ki] = bs[(size_t)(m0+mi)*NN + k0 + ki];
    }
    __syncthreads();
    for (int e = tid; e < 1024; e += 256){
        int ki = e>>5, mi = e&31;   // mi == lane
        float d = sbs[mi][ki];
        #pragma unroll
        for (int f=0; f<16; f++) d += Lm[mi][f]*Rk[ki][f];
        float s = 0.5f*tanh_ap(0.5f*d);
        __half h = q2048(s);
        int kg = k0 + ki;
        int mg = m0 + mi;
        int xb = kg>>7, r = kg&127, ch = mg>>6, sg = mg&63;
        size_t tb = ((size_t)(b*32 + xb)*63 + ch)*16384;
        uint32_t off = SWZ((uint32_t)(r*128 + sg*2));
        *(__half*)(g_Bt + tb + off) = h;
        // colsum of the STORED (quantized) value => correction consistent with GEMM
        float cs = __half2float(h);
        #pragma unroll
        for (int off2=16; off2>0; off2>>=1) cs += __shfl_down_sync(0xFFFFFFFFu, cs, off2);
        if (lane==0) atomicAdd(&g_colsum[b*NN + kg], cs);
    }
}

#define KCHUNK 64
#define NCHUNK 63
#define NSTAGE 3
#define STG_BYTES 65536
#define OFF_AH 0
#define OFF_AL 16384
#define OFF_BH 32768
#define OFF_BL 49152
#define SMEM_REQ (NSTAGE*STG_BYTES + 1024)
// fp16 single-pass gemm_S: 32KB stages
#define S_STG 32768
#define SMEM_REQ_S (NSTAGE*S_STG + 2048)

// ---- big GEMM: single-pass fp16, bulk-TMA fed, 2 CTAs/SM ----
__global__ void __launch_bounds__(256,2) gemm_S_mma(){
    extern __shared__ char dsm[];
    uint32_t sb = (smem_u32(dsm) + 1023u) & ~1023u;
    uint32_t mb = sb + NSTAGE*S_STG;   // 3 mbarriers
    int tid = threadIdx.x, lane = tid&31, wid = tid>>5;
    int b = blockIdx.z;
    int yb = blockIdx.y, xb = blockIdx.x;
    int mBase = yb*128, nBase = xb*128;
    int wm = wid>>1, wn = wid&1;

    const unsigned char* Asrc = g_At + (size_t)yb*63*16384;
    const unsigned char* Bsrc = g_Bt + ((size_t)(b*32 + xb))*63*16384;

    if (tid==0){
        mbar_init(mb,1); mbar_init(mb+8,1); mbar_init(mb+16,1);
    }
    __syncthreads();
    if (tid==0){
        #pragma unroll
        for (int p=0;p<NSTAGE;p++){
            uint32_t bar = mb + p*8;
            mbar_expect_tx(bar, 32768);
            tma_bulk_g2s(sb + p*S_STG,          Asrc + (size_t)p*16384, 16384, bar);
            tma_bulk_g2s(sb + p*S_STG + 16384,  Bsrc + (size_t)p*16384, 16384, bar);
        }
    }

    float acc[2][8][4];
    #pragma unroll
    for (int i=0;i<2;i++)
        #pragma unroll
        for (int j=0;j<8;j++)
            #pragma unroll
            for (int q=0;q<4;q++) acc[i][j][q]=0.f;

    for (int c=0;c<NCHUNK;c++){
        int s = c%NSTAGE;
        mbar_wait(mb + s*8, (uint32_t)((c/NSTAGE)&1));
        uint32_t stg = sb + s*S_STG;
        #pragma unroll
        for (int ks=0;ks<4;ks++){
            uint32_t ah[2][4];
            #pragma unroll
            for (int mt=0;mt<2;mt++){
                int row = wm*32 + mt*16 + (lane&15);
                uint32_t bo = SWZ(row*128 + ks*32 + (lane>>4)*16);
                ldsm4(ah[mt], stg + bo);
            }
            uint32_t bh[8][2];
            #pragma unroll
            for (int nt=0;nt<8;nt++){
                int row = wn*64 + nt*8 + (lane&7);
                uint32_t bo = SWZ(row*128 + ks*32 + ((lane>>3)&1)*16);
                ldsm2(bh[nt], stg + 16384 + bo);
            }
            #pragma unroll
            for (int mt=0;mt<2;mt++)
                #pragma unroll
                for (int nt=0;nt<8;nt++)
                    mma16816h(acc[mt][nt], ah[mt], bh[nt]);
        }
        __syncthreads();
        if (tid==0 && (c+NSTAGE) < NCHUNK){
            int cn = c+NSTAGE;
            uint32_t bar = mb + s*8;
            mbar_expect_tx(bar, 32768);
            tma_bulk_g2s(stg,          Asrc + (size_t)cn*16384, 16384, bar);
            tma_bulk_g2s(stg + 16384,  Bsrc + (size_t)cn*16384, 16384, bar);
        }
    }

    float* C = g_S + (size_t)b*NN*NN;
    const float* CS = g_colsum + b*NN;
    int tig = lane&3, grp = lane>>2;
    #pragma unroll
    for (int mt=0;mt<2;mt++){
        int r0 = mBase + wm*32 + mt*16 + grp;
        int r1 = r0 + 8;
        #pragma unroll
        for (int nt=0;nt<8;nt++){
            int c0 = nBase + wn*64 + nt*8 + tig*2;
            if (c0 < NN){
                bool c1ok = (c0+1) < NN;
                float cs0 = 0.5f*CS[c0];
                float cs1 = c1ok ? 0.5f*CS[c0+1] : 0.f;
                if (r0 < NN){
                    C[(size_t)r0*NN + c0] = acc[mt][nt][0] + cs0;
                    if (c1ok) C[(size_t)r0*NN + c0 + 1] = acc[mt][nt][1] + cs1;
                }
                if (r1 < NN){
                    C[(size_t)r1*NN + c0] = acc[mt][nt][2] + cs0;
                    if (c1ok) C[(size_t)r1*NN + c0 + 1] = acc[mt][nt][3] + cs1;
                }
            }
        }
    }
}

// ---- generic bf16-split tensor GEMM (3-pass), 256 threads, for the small GEMMs ----
__global__ void __launch_bounds__(256,1) gemm_bsplit(
    const __nv_bfloat16* __restrict__ gAh, const __nv_bfloat16* __restrict__ gAl, long long sAb,
    const __nv_bfloat16* __restrict__ gBh, const __nv_bfloat16* __restrict__ gBl, long long sBb,
    float* __restrict__ gC, const float* __restrict__ gD, long long sCb,
    int ldc, int Ncols, float alpha, float beta)
{
    extern __shared__ char dsm[];
    uint32_t sb = (smem_u32(dsm) + 1023u) & ~1023u;
    int tid = threadIdx.x, lane = tid&31, wid = tid>>5;
    int b = blockIdx.z;
    int mBase = blockIdx.y*128, nBase = blockIdx.x*128;
    int wm = wid>>1, wn = wid&1;

    const __nv_bfloat16* Ahp = gAh + (size_t)b*sAb;
    const __nv_bfloat16* Alp = gAl + (size_t)b*sAb;
    const __nv_bfloat16* Bhp = gBh + (size_t)b*sBb;
    const __nv_bfloat16* Blp = gBl + (size_t)b*sBb;

    float acc[2][8][4];
    #pragma unroll
    for (int i=0;i<2;i++)
        #pragma unroll
        for (int j=0;j<8;j++)
            #pragma unroll
            for (int q=0;q<4;q++) acc[i][j][q]=0.f;

    #define ISSUE_STAGE(c_) do{ \
        int st_ = (c_)%NSTAGE; uint32_t stg_ = sb + st_*STG_BYTES; \
        int k0_ = (c_)*KCHUNK; \
        _Pragma("unroll") \
        for (int j_=0;j_<4;j_++){ \
            int op_ = j_*256+tid; int row_ = op_>>3, ch_ = op_&7; \
            int kk_ = k0_ + ch_*8; \
            uint32_t so_ = SWZ(row_*128 + ch_*16); \
            bool va_ = (kk_ < NN) && ((mBase+row_) < NN); \
            size_t ga_ = va_ ? ((size_t)(mBase+row_)*NN + kk_) : 0; \
            cpa16(stg_+OFF_AH+so_, Ahp+ga_, va_); \
            cpa16(stg_+OFF_AL+so_, Alp+ga_, va_); \
            bool vb_ = (kk_ < NN) && ((nBase+row_) < Ncols); \
            size_t gb_ = vb_ ? ((size_t)(nBase+row_)*NN + kk_) : 0; \
            cpa16(stg_+OFF_BH+so_, Bhp+gb_, vb_); \
            cpa16(stg_+OFF_BL+so_, Blp+gb_, vb_); \
        } \
        cpa_commit(); \
    }while(0)

    ISSUE_STAGE(0);
    ISSUE_STAGE(1);
    ISSUE_STAGE(2);

    for (int c=0;c<NCHUNK;c++){
        asm volatile("cp.async.wait_group 2;" ::: "memory");
        __syncthreads();
        uint32_t stg = sb + (c%NSTAGE)*STG_BYTES;
        #pragma unroll
        for (int ks=0;ks<4;ks++){
            uint32_t ah[2][4], al[2][4];
            #pragma unroll
            for (int mt=0;mt<2;mt++){
                int row = wm*32 + mt*16 + (lane&15);
                uint32_t bo = SWZ(row*128 + ks*32 + (lane>>4)*16);
                ldsm4(ah[mt], stg+OFF_AH+bo);
                ldsm4(al[mt], stg+OFF_AL+bo);
            }
            uint32_t bh[8][2], bl[8][2];
            #pragma unroll
            for (int nt=0;nt<8;nt++){
                int row = wn*64 + nt*8 + (lane&7);
                uint32_t bo = SWZ(row*128 + ks*32 + ((lane>>3)&1)*16);
                ldsm2(bh[nt], stg+OFF_BH+bo);
                ldsm2(bl[nt], stg+OFF_BL+bo);
            }
            #pragma unroll
            for (int mt=0;mt<2;mt++)
                #pragma unroll
                for (int nt=0;nt<8;nt++){
                    mma16816(acc[mt][nt], ah[mt], bh[nt]);
                    mma16816(acc[mt][nt], ah[mt], bl[nt]);
                    mma16816(acc[mt][nt], al[mt], bh[nt]);
                }
        }
        __syncthreads();
        if (c+NSTAGE < NCHUNK){ ISSUE_STAGE(c+NSTAGE); }
        else { cpa_commit(); }
    }
    #undef ISSUE_STAGE

    float* C = gC + (size_t)b*sCb;
    const float* D = gD ? gD + (size_t)b*sCb : (const float*)0;
    int tig = lane&3, grp = lane>>2;
    #pragma unroll
    for (int mt=0;mt<2;mt++){
        int r0 = mBase + wm*32 + mt*16 + grp;
        int r1 = r0 + 8;
        #pragma unroll
        for (int nt=0;nt<8;nt++){
            int c0 = nBase + wn*64 + nt*8 + tig*2;
            if (c0 < Ncols){
                bool c1ok = (c0+1) < Ncols;
                if (r0 < NN){
                    float v0 = alpha*acc[mt][nt][0];
                    if (D) v0 += beta*D[(size_t)r0*ldc + c0];
                    C[(size_t)r0*ldc + c0] = v0;
                    if (c1ok){
                        float v1 = alpha*acc[mt][nt][1];
                        if (D) v1 += beta*D[(size_t)r0*ldc + c0 + 1];
                        C[(size_t)r0*ldc + c0 + 1] = v1;
                    }
                }
                if (r1 < NN){
                    float v2 = alpha*acc[mt][nt][2];
                    if (D) v2 += beta*D[(size_t)r1*ldc + c0];
                    C[(size_t)r1*ldc + c0] = v2;
                    if (c1ok){
                        float v3 = alpha*acc[mt][nt][3];
                        if (D) v3 += beta*D[(size_t)r1*ldc + c0 + 1];
                        C[(size_t)r1*ldc + c0 + 1] = v3;
                    }
                }
            }
        }
    }
}

// softmax over last dim of S; writes bf16 h/l split (A operand of xSAtt)
__global__ void k_softmax(){
    __shared__ float row[NN];
    __shared__ float red[256];
    int tid = threadIdx.x;
    size_t base = (size_t)blockIdx.x * NN;
    float m = -1e30f;
    for (int i = tid; i < NN; i += 256){ float v = g_S[base+i]; row[i]=v; m = fmaxf(m,v); }
    red[tid]=m; __syncthreads();
    for (int o=128;o>0;o>>=1){ if (tid<o) red[tid]=fmaxf(red[tid],red[tid+o]); __syncthreads(); }
    m = red[0]; __syncthreads();
    float s = 0.f;
    for (int i = tid; i < NN; i += 256){ float e = __expf(row[i]-m); row[i]=e; s += e; }
    red[tid]=s; __syncthreads();
    for (int o=128;o>0;o>>=1){ if (tid<o) red[tid]+=red[tid+o]; __syncthreads(); }
    float inv = 1.f/red[0];
    for (int i = tid; i < NN; i += 256){
        float p = row[i]*inv;
        __nv_bfloat16 h = __float2bfloat16(p);
        g_spT_h[base+i] = h;
        g_spT_l[base+i] = __float2bfloat16(p - __bfloat162float(h));
    }
}

__global__ void k_final(const float* __restrict__ x, const float* __restrict__ cheb,
                        const float* __restrict__ tw, const float* __restrict__ tb){
    int bn = blockIdx.x;
    int tid = threadIdx.x;
    __shared__ float xs[256], t0[256], t1[256], t2[256], ts0[16], ts1[16], ts2[16];
    size_t rb = (size_t)bn*256;
    xs[tid]=x[rb+tid]; t0[tid]=g_Tx0[rb+tid]; t1[tid]=g_Tx1[rb+tid]; t2[tid]=g_Tx2[rb+tid];
    __syncthreads();
    if (tid < 48){
        int kk = tid>>4, f = tid&15;
        const float* src = (kk==0) ? t0 : ((kk==1) ? t1 : t2);
        float s = 0.f;
        #pragma unroll
        for (int t=0;t<16;t++) s += src[f*16+t];
        float* dst = (kk==0) ? ts0 : ((kk==1) ? ts1 : ts2);
        dst[f] = s;
    }
    __syncthreads();
    if (tid < 16){
        int o = tid;
        float tm = 0.f;
        #pragma unroll
        for (int c=0;c<16;c++)
            #pragma unroll
            for (int t=0;t<16;t++) tm += xs[c*16+t]*tw[(o*16+c)*16+t];
        float sp = 0.f;
        #pragma unroll
        for (int f=0;f<16;f++)
            sp += ts0[f]*cheb[f*16+o] + ts1[f]*cheb[256+f*16+o] + ts2[f]*cheb[512+f*16+o];
        g_y[bn*16+o] = sp*(1.f/16.f) + tm + tb[o] + xs[o*16+15];
    }
}

__global__ void k_stats(){
    int b = blockIdx.x, tid = threadIdx.x;
    double s = 0.0, ss = 0.0;
    for (int i = tid; i < NN*OO; i += 256){
        float v = g_y[b*NN*OO + i];
        s += (double)v; ss += (double)v*(double)v;
    }
    __shared__ double rs[256], rq[256];
    rs[tid]=s; rq[tid]=ss; __syncthreads();
    for (int o=128;o>0;o>>=1){ if (tid<o){ rs[tid]+=rs[tid+o]; rq[tid]+=rq[tid+o]; } __syncthreads(); }
    if (tid==0){
        double mean = rs[0]/(double)(NN*OO);
        double var  = rq[0]/(double)(NN*OO) - mean*mean;
        g_stats[b*2]   = (float)mean;
        g_stats[b*2+1] = (float)(1.0/sqrt(var + 1e-5));
    }
}
__global__ void k_out(const float* __restrict__ lng, const float* __restrict__ lnb,
                      float* __restrict__ out){
    int i = blockIdx.x*256 + threadIdx.x;
    if (i < BB*NN*OO){
        int b  = i / (NN*OO);
        int no = i % (NN*OO);
        float v = (g_y[i]-g_stats[b*2])*g_stats[b*2+1]*lng[no] + lnb[no];
        out[i] = fmaxf(v, 0.f);
    }
}

extern "C" void kernel_launch(void* const* d_in, const int* in_sizes, int n_in,
                              void* d_out, int out_size){
    const float* x    = (const float*)d_in[0];
    const float* lap  = (const float*)d_in[1];
    const float* W1   = (const float*)d_in[2];
    const float* W2   = (const float*)d_in[3];
    const float* W3   = (const float*)d_in[4];
    const float* bs   = (const float*)d_in[5];
    const float* Vs   = (const float*)d_in[6];
    const float* U1   = (const float*)d_in[7];
    const float* U2   = (const float*)d_in[8];
    const float* U3   = (const float*)d_in[9];
    const float* be   = (const float*)d_in[10];
    const float* Ve   = (const float*)d_in[11];
    const float* cheb = (const float*)d_in[12];
    const float* tw   = (const float*)d_in[13];
    const float* tb   = (const float*)d_in[14];
    const float* lng  = (const float*)d_in[15];
    const float* lnb  = (const float*)d_in[16];
    float* out = (float*)d_out;

    static int smem_set = 0;
    if (!smem_set){
        cudaFuncSetAttribute(gemm_bsplit, cudaFuncAttributeMaxDynamicSharedMemorySize, SMEM_REQ);
        cudaFuncSetAttribute(gemm_S_mma,  cudaFuncAttributeMaxDynamicSharedMemorySize, SMEM_REQ_S);
        smem_set = 1;
    }

    float *g_T0p, *g_T1p, *g_T2p, *g_xTp;
    __nv_bfloat16 *spT_h_p, *spT_l_p, *lap_h_p, *lap_l_p, *bT_h_p, *bT_l_p;
    cudaGetSymbolAddress((void**)&g_T0p, g_Tx0);
    cudaGetSymbolAddress((void**)&g_T1p, g_Tx1);
    cudaGetSymbolAddress((void**)&g_T2p, g_Tx2);
    cudaGetSymbolAddress((void**)&g_xTp, g_xTAt);
    cudaGetSymbolAddress((void**)&spT_h_p, g_spT_h);
    cudaGetSymbolAddress((void**)&spT_l_p, g_spT_l);
    cudaGetSymbolAddress((void**)&lap_h_p, g_lap_h);
    cudaGetSymbolAddress((void**)&lap_l_p, g_lap_l);
    cudaGetSymbolAddress((void**)&bT_h_p,  g_bT_h);
    cudaGetSymbolAddress((void**)&bT_l_p,  g_bT_l);

    k_u2u3<<<(NN+255)/256, 256>>>(U2, U3);
    k_tred<<<BB*TT, 256>>>(x, U1);
    k_E<<<1, 256>>>(Ve, be);
    k_xTAt<<<BB*NN, 256>>>(x, W1, W2, W3);
    k_vs_tiled<<<(NN*NN+255)/256, 256>>>(Vs);
    k_lap_split<<<(NN*NN+255)/256, 256>>>(lap);
    k_zero_cs<<<(BB*NN+255)/256, 256>>>();
    k_sigP<<<dim3(125,125,BB), 256>>>(bs);

    // S = (Vs-.5)@(sig-.5) + 0.5*colsum   (single-pass fp16, bulk-TMA fed, occ 2)
    gemm_S_mma<<<dim3(32,32,BB), 256, SMEM_REQ_S>>>();

    k_softmax<<<BB*NN, 256>>>();
    k_tsplit<<<dim3(125,8,BB), 256>>>(g_xTp);

    gemm_bsplit<<<dim3(2,32,BB), 256, SMEM_REQ>>>(
        spT_h_p, spT_l_p, (long long)NN*NN, bT_h_p, bT_l_p, (long long)256*NN,
        g_T0p, (const float*)0, (long long)NN*256, 256, 256, 1.f, 0.f);

    k_tsplit<<<dim3(125,8,BB), 256>>>(g_T0p);

    gemm_bsplit<<<dim3(2,32,BB), 256, SMEM_REQ>>>(
        lap_h_p, lap_l_p, 0LL, bT_h_p, bT_l_p, (long long)256*NN,
        g_T1p, (const float*)0, (long long)NN*256, 256, 256, 1.f, 0.f);

    k_tsplit<<<dim3(125,8,BB), 256>>>(g_T1p);

    gemm_bsplit<<<dim3(2,32,BB), 256, SMEM_REQ>>>(
        lap_h_p, lap_l_p, 0LL, bT_h_p, bT_l_p, (long long)256*NN,
        g_T2p, g_T0p, (long long)NN*256, 256, 256, 2.f, -1.f);

    k_final<<<BB*NN, 256>>>(x, cheb, tw, tb);
    k_stats<<<BB, 256>>>();
    k_out<<<(BB*NN*OO+255)/256, 256>>>(lng, lnb, out);
}

// round 13
// speedup vs baseline: 5.6840x; 1.2607x over previous
#include <cuda_runtime.h>
#include <cuda_bf16.h>
#include <cuda_fp16.h>
#include <math.h>
#include <stdint.h>

#define NN 4000
#define BB 4
#define FF 16
#define TT 16
#define OO 16

__device__ float g_u2u3[NN];
__device__ float g_tlhs[BB*TT];
__device__ float g_trhs[BB*TT];
__device__ float g_E[BB*TT*TT];
__device__ float g_xTAt[BB*NN*FF*TT];
__device__ float g_slhs[BB*NN*FF];
__device__ float g_srhs[BB*NN*FF];
// pre-swizzled chunk-tiled fp16 operands (zero-init => padding stays 0 forever)
__device__ __align__(256) unsigned char g_At[(size_t)32*63*16384];        // Vs-0.5 [yb][ch]
__device__ __align__(256) unsigned char g_Bt[(size_t)BB*32*63*16384];     // (sig-0.5)^T [b][xb][ch]
__device__ __align__(256) unsigned char g_PT[(size_t)BB*32*63*16384];     // softmax(S) [b][yb][ch]
__device__ __align__(256) unsigned char g_lapT[(size_t)32*63*16384];      // laplacian [yb][ch]
__device__ __align__(256) unsigned char g_bTt[(size_t)BB*2*63*16384];     // transposed B panels [b][xb][ch]
__device__ float g_colsum[BB*NN];
__device__ __align__(256) float g_S[(size_t)BB*NN*NN];
__device__ float g_Tx0[BB*NN*FF*TT];
__device__ float g_Tx1[BB*NN*FF*TT];
__device__ float g_Tx2[BB*NN*FF*TT];
__device__ float g_y[BB*NN*OO];
__device__ float g_stats[BB*2];

__device__ __forceinline__ float tanh_ap(float x){
    float y; asm("tanh.approx.f32 %0, %1;" : "=f"(y) : "f"(x)); return y;
}
__device__ __forceinline__ uint32_t smem_u32(const void* p){
    uint32_t a;
    asm("{ .reg .u64 t; cvta.to.shared.u64 t, %1; cvt.u32.u64 %0, t; }" : "=r"(a) : "l"(p));
    return a;
}
#define SWZ(o) ((uint32_t)(o) ^ ((((uint32_t)(o)) >> 3) & 0x70u))
__device__ __forceinline__ void ldsm4(uint32_t* r, uint32_t addr){
    asm volatile("ldmatrix.sync.aligned.m8n8.x4.shared.b16 {%0,%1,%2,%3}, [%4];"
        : "=r"(r[0]),"=r"(r[1]),"=r"(r[2]),"=r"(r[3]) : "r"(addr));
}
__device__ __forceinline__ void ldsm2(uint32_t* r, uint32_t addr){
    asm volatile("ldmatrix.sync.aligned.m8n8.x2.shared.b16 {%0,%1}, [%2];"
        : "=r"(r[0]),"=r"(r[1]) : "r"(addr));
}
__device__ __forceinline__ void mma16816h(float* c, const uint32_t* a, const uint32_t* b){
    asm volatile("mma.sync.aligned.m16n8k16.row.col.f32.f16.f16.f32 "
        "{%0,%1,%2,%3}, {%4,%5,%6,%7}, {%8,%9}, {%0,%1,%2,%3};"
        : "+f"(c[0]),"+f"(c[1]),"+f"(c[2]),"+f"(c[3])
        : "r"(a[0]),"r"(a[1]),"r"(a[2]),"r"(a[3]), "r"(b[0]),"r"(b[1]));
}
__device__ __forceinline__ void mbar_init(uint32_t a, uint32_t cnt){
    asm volatile("mbarrier.init.shared.b64 [%0], %1;" :: "r"(a), "r"(cnt) : "memory");
}
__device__ __forceinline__ void mbar_expect_tx(uint32_t a, uint32_t bytes){
    asm volatile("mbarrier.arrive.expect_tx.shared.b64 _, [%0], %1;" :: "r"(a), "r"(bytes) : "memory");
}
__device__ __forceinline__ void mbar_wait(uint32_t a, uint32_t ph){
    uint32_t done;
    asm volatile("{\n\t.reg .pred p;\n\t"
        "mbarrier.try_wait.parity.acquire.cta.shared::cta.b64 p, [%1], %2;\n\t"
        "selp.b32 %0, 1, 0, p;\n\t}" : "=r"(done) : "r"(a), "r"(ph) : "memory");
    if (!done){
        asm volatile("{\n\t.reg .pred P1;\n\t"
            "WL%=:\n\t"
            "mbarrier.try_wait.parity.acquire.cta.shared::cta.b64 P1, [%0], %1, 0x989680;\n\t"
            "@P1 bra.uni WD%=;\n\t"
            "bra.uni WL%=;\n\t"
            "WD%=:\n\t}" :: "r"(a), "r"(ph) : "memory");
    }
}
__device__ __forceinline__ void tma_bulk_g2s(uint32_t dst, const void* src, uint32_t bytes, uint32_t mbar){
    asm volatile("cp.async.bulk.shared::cluster.global.mbarrier::complete_tx::bytes [%0], [%1], %2, [%3];"
        :: "r"(dst), "l"(src), "r"(bytes), "r"(mbar) : "memory");
}
// exact 11-bit fixed-point quantization to fp16 (values in [-0.5,0.5])
__device__ __forceinline__ __half q2048(float v){
    int q = __float2int_rn(v*2048.f);
    return __float2half_rn((float)q * (1.f/2048.f));
}

// ---- small kernels ----
__global__ void k_u2u3(const float* __restrict__ U2, const float* __restrict__ U3){
    int n = blockIdx.x*blockDim.x + threadIdx.x;
    if (n < NN){
        float s = 0.f;
        #pragma unroll
        for (int g=0; g<FF; g++) s += U2[g*NN+n]*U3[g];
        g_u2u3[n] = s;
    }
}
__global__ void k_tred(const float* __restrict__ x, const float* __restrict__ U1){
    int b = blockIdx.x >> 4, t = blockIdx.x & 15;
    int tid = threadIdx.x;
    float s1 = 0.f, s2 = 0.f;
    for (int i = tid; i < NN*FF; i += 256){
        int n = i >> 4, f = i & 15;
        float v = x[((size_t)(b*NN+n)*FF+f)*TT + t];
        s1 += v*U1[n]; s2 += v*g_u2u3[n];
    }
    __shared__ float r1[256], r2[256];
    r1[tid]=s1; r2[tid]=s2; __syncthreads();
    for (int o=128; o>0; o>>=1){
        if (tid<o){ r1[tid]+=r1[tid+o]; r2[tid]+=r2[tid+o]; }
        __syncthreads();
    }
    if (tid==0){ g_tlhs[b*TT+t]=r1[0]; g_trhs[b*TT+t]=r2[0]; }
}
__global__ void k_E(const float* __restrict__ Ve, const float* __restrict__ be){
    __shared__ float tl[BB*TT], tr[BB*TT], sVe[TT*TT], sbe[TT*TT], Eb[BB*TT*TT];
    int tid = threadIdx.x;
    if (tid < BB*TT){ tl[tid]=g_tlhs[tid]; tr[tid]=g_trhs[tid]; }
    if (tid < TT*TT){ sVe[tid]=Ve[tid]; sbe[tid]=be[tid]; }
    __syncthreads();
    for (int idx = tid; idx < BB*TT*TT; idx += 256){
        int b = idx>>8, t = (idx>>4)&15, r = idx&15;
        float s = 0.f;
        #pragma unroll
        for (int ss=0; ss<TT; ss++)
            s += sVe[t*TT+ss]*(1.f/(1.f+expf(-(tl[b*TT+ss]*tr[b*TT+r] + sbe[ss*TT+r]))));
        Eb[idx] = s;
    }
    __syncthreads();
    if (tid < BB*TT){
        int base = tid*TT;
        float m = -1e30f;
        for (int r=0;r<TT;r++) m = fmaxf(m, Eb[base+r]);
        float e[TT]; float sum = 0.f;
        for (int r=0;r<TT;r++){ e[r]=expf(Eb[base+r]-m); sum+=e[r]; }
        float inv = 1.f/sum;
        for (int r=0;r<TT;r++) g_E[base+r] = e[r]*inv;
    }
}
__global__ void k_xTAt(const float* __restrict__ x, const float* __restrict__ W1,
                       const float* __restrict__ W2, const float* __restrict__ W3){
    int bn = blockIdx.x;
    int b = bn / NN;
    int tid = threadIdx.x;
    __shared__ float xs[256], Es[256], sr0[16];
    xs[tid] = x[(size_t)bn*256 + tid];
    Es[tid] = g_E[b*256 + tid];
    __syncthreads();
    int f = tid >> 4, t = tid & 15;
    float s = 0.f;
    #pragma unroll
    for (int ss=0; ss<TT; ss++) s += Es[t*16+ss]*xs[f*16+ss];
    g_xTAt[(size_t)bn*256 + tid] = s;
    if (tid < 16){
        float a=0.f, c=0.f;
        #pragma unroll
        for (int t2=0;t2<16;t2++){ float v = xs[tid*16+t2]; a += v*W1[t2]; c += v*W3[t2]; }
        g_slhs[bn*16+tid] = a;
        sr0[tid] = c;
    }
    __syncthreads();
    if (tid < 16){
        float g = 0.f;
        #pragma unroll
        for (int kk=0;kk<16;kk++) g += W2[tid*16+kk]*sr0[kk];
        g_srhs[bn*16+tid] = g;
    }
}
__global__ void k_vs_tiled(const float* __restrict__ Vs){
    size_t i = (size_t)blockIdx.x*256 + threadIdx.x;
    if (i < (size_t)NN*NN){
        int n = (int)(i / NN), m = (int)(i % NN);
        __half h = q2048(Vs[i] - 0.5f);
        int yb = n>>7, r = n&127, ch = m>>6, sg = m&63;
        size_t tb = ((size_t)yb*63 + ch)*16384;
        uint32_t off = SWZ((uint32_t)(r*128 + sg*2));
        *(__half*)(g_At + tb + off) = h;
    }
}
// laplacian -> fp16 tiled A layout
__global__ void k_lap_tiled(const float* __restrict__ lap){
    size_t i = (size_t)blockIdx.x*256 + threadIdx.x;
    if (i < (size_t)NN*NN){
        int n = (int)(i / NN), m = (int)(i % NN);
        __half h = __float2half_rn(lap[i]);
        int yb = n>>7, r = n&127, ch = m>>6, sg = m&63;
        size_t tb = ((size_t)yb*63 + ch)*16384;
        uint32_t off = SWZ((uint32_t)(r*128 + sg*2));
        *(__half*)(g_lapT + tb + off) = h;
    }
}
__global__ void k_zero_cs(){
    int i = blockIdx.x*256 + threadIdx.x;
    if (i < BB*NN) g_colsum[i] = 0.f;
}
// transpose: X [b][NN][256] fp32 -> fp16 tiled B panels [b][xb][ch]
__global__ void k_tsplit(const float* __restrict__ X){
    int b = blockIdx.z;
    int m0 = blockIdx.x*32, c0 = blockIdx.y*32;
    int tx = threadIdx.x & 31, ty = threadIdx.x >> 5;
    __shared__ float t[32][33];
    const float* Xb = X + (size_t)b*NN*256;
    #pragma unroll
    for (int i=0;i<4;i++){
        int row = ty + i*8;
        t[row][tx] = Xb[(size_t)(m0+row)*256 + c0 + tx];
    }
    __syncthreads();
    #pragma unroll
    for (int i=0;i<4;i++){
        int row = ty + i*8;
        int c = c0 + row;      // output col 0..255
        int m = m0 + tx;       // contraction index
        __half h = __float2half_rn(t[tx][row]);
        int xb = c>>7, r = c&127, ch = m>>6, sg = m&63;
        size_t tb = ((size_t)(b*2 + xb)*63 + ch)*16384;
        uint32_t off = SWZ((uint32_t)(r*128 + sg*2));
        *(__half*)(g_bTt + tb + off) = h;
    }
}
// (sigmoid-0.5)=0.5*tanh(d/2), quantized fp16, tiled [b][xb][ch], colsum of stored value
__global__ void k_sigP(const float* __restrict__ bs){
    int b = blockIdx.z;
    int m0 = blockIdx.y*32, k0 = blockIdx.x*32;
    int tid = threadIdx.x, lane = tid&31;
    __shared__ float Lm[32][17], Rk[32][17], sbs[32][33];
    for (int i = tid; i < 512; i += 256){
        int r = i>>4, c = i&15;
        Lm[r][c] = g_slhs[(b*NN + m0 + r)*16 + c];
        Rk[r][c] = g_srhs[(b*NN + k0 + r)*16 + c];
    }
    for (int i = tid; i < 1024; i += 256){
        int mi = i>>5, ki = i&31;
        sbs[mi][ki] = bs[(size_t)(m0+mi)*NN + k0 + ki];
    }
    __syncthreads();
    for (int e = tid; e < 1024; e += 256){
        int ki = e>>5, mi = e&31;
        float d = sbs[mi][ki];
        #pragma unroll
        for (int f=0; f<16; f++) d += Lm[mi][f]*Rk[ki][f];
        float s = 0.5f*tanh_ap(0.5f*d);
        __half h = q2048(s);
        int kg = k0 + ki;
        int mg = m0 + mi;
        int xb = kg>>7, r = kg&127, ch = mg>>6, sg = mg&63;
        size_t tb = ((size_t)(b*32 + xb)*63 + ch)*16384;
        uint32_t off = SWZ((uint32_t)(r*128 + sg*2));
        *(__half*)(g_Bt + tb + off) = h;
        float cs = __half2float(h);
        #pragma unroll
        for (int off2=16; off2>0; off2>>=1) cs += __shfl_down_sync(0xFFFFFFFFu, cs, off2);
        if (lane==0) atomicAdd(&g_colsum[b*NN + kg], cs);
    }
}

#define NCHUNK 63
#define NSTAGE 3
#define S_STG 32768
#define SMEM_REQ_S (NSTAGE*S_STG + 2048)

// ---- big GEMM: single-pass fp16, bulk-TMA fed, occ 2, colsum epilogue ----
__global__ void __launch_bounds__(256,2) gemm_S_mma(){
    extern __shared__ char dsm[];
    uint32_t sb = (smem_u32(dsm) + 1023u) & ~1023u;
    uint32_t mb = sb + NSTAGE*S_STG;
    int tid = threadIdx.x, lane = tid&31, wid = tid>>5;
    int b = blockIdx.z;
    int yb = blockIdx.y, xb = blockIdx.x;
    int mBase = yb*128, nBase = xb*128;
    int wm = wid>>1, wn = wid&1;

    const unsigned char* Asrc = g_At + (size_t)yb*63*16384;
    const unsigned char* Bsrc = g_Bt + ((size_t)(b*32 + xb))*63*16384;

    if (tid==0){ mbar_init(mb,1); mbar_init(mb+8,1); mbar_init(mb+16,1); }
    __syncthreads();
    if (tid==0){
        #pragma unroll
        for (int p=0;p<NSTAGE;p++){
            uint32_t bar = mb + p*8;
            mbar_expect_tx(bar, 32768);
            tma_bulk_g2s(sb + p*S_STG,          Asrc + (size_t)p*16384, 16384, bar);
            tma_bulk_g2s(sb + p*S_STG + 16384,  Bsrc + (size_t)p*16384, 16384, bar);
        }
    }

    float acc[2][8][4];
    #pragma unroll
    for (int i=0;i<2;i++)
        #pragma unroll
        for (int j=0;j<8;j++)
            #pragma unroll
            for (int q=0;q<4;q++) acc[i][j][q]=0.f;

    for (int c=0;c<NCHUNK;c++){
        int s = c%NSTAGE;
        mbar_wait(mb + s*8, (uint32_t)((c/NSTAGE)&1));
        uint32_t stg = sb + s*S_STG;
        #pragma unroll
        for (int ks=0;ks<4;ks++){
            uint32_t ah[2][4];
            #pragma unroll
            for (int mt=0;mt<2;mt++){
                int row = wm*32 + mt*16 + (lane&15);
                uint32_t bo = SWZ(row*128 + ks*32 + (lane>>4)*16);
                ldsm4(ah[mt], stg + bo);
            }
            uint32_t bh[8][2];
            #pragma unroll
            for (int nt=0;nt<8;nt++){
                int row = wn*64 + nt*8 + (lane&7);
                uint32_t bo = SWZ(row*128 + ks*32 + ((lane>>3)&1)*16);
                ldsm2(bh[nt], stg + 16384 + bo);
            }
            #pragma unroll
            for (int mt=0;mt<2;mt++)
                #pragma unroll
                for (int nt=0;nt<8;nt++)
                    mma16816h(acc[mt][nt], ah[mt], bh[nt]);
        }
        __syncthreads();
        if (tid==0 && (c+NSTAGE) < NCHUNK){
            int cn = c+NSTAGE;
            uint32_t bar = mb + s*8;
            mbar_expect_tx(bar, 32768);
            tma_bulk_g2s(stg,          Asrc + (size_t)cn*16384, 16384, bar);
            tma_bulk_g2s(stg + 16384,  Bsrc + (size_t)cn*16384, 16384, bar);
        }
    }

    float* C = g_S + (size_t)b*NN*NN;
    const float* CS = g_colsum + b*NN;
    int tig = lane&3, grp = lane>>2;
    #pragma unroll
    for (int mt=0;mt<2;mt++){
        int r0 = mBase + wm*32 + mt*16 + grp;
        int r1 = r0 + 8;
        #pragma unroll
        for (int nt=0;nt<8;nt++){
            int c0 = nBase + wn*64 + nt*8 + tig*2;
            if (c0 < NN){
                bool c1ok = (c0+1) < NN;
                float cs0 = 0.5f*CS[c0];
                float cs1 = c1ok ? 0.5f*CS[c0+1] : 0.f;
                if (r0 < NN){
                    C[(size_t)r0*NN + c0] = acc[mt][nt][0] + cs0;
                    if (c1ok) C[(size_t)r0*NN + c0 + 1] = acc[mt][nt][1] + cs1;
                }
                if (r1 < NN){
                    C[(size_t)r1*NN + c0] = acc[mt][nt][2] + cs0;
                    if (c1ok) C[(size_t)r1*NN + c0 + 1] = acc[mt][nt][3] + cs1;
                }
            }
        }
    }
}

// ---- small GEMM: same skeleton, parametrized A/B tiled sources, alpha/beta epilogue ----
__global__ void __launch_bounds__(256,2) gemm_sm(
    const unsigned char* __restrict__ Abase, long long sAb,
    const unsigned char* __restrict__ Bbase, long long sBb,
    float* __restrict__ gC, const float* __restrict__ gD,
    float alpha, float beta)
{
    extern __shared__ char dsm[];
    uint32_t sb = (smem_u32(dsm) + 1023u) & ~1023u;
    uint32_t mb = sb + NSTAGE*S_STG;
    int tid = threadIdx.x, lane = tid&31, wid = tid>>5;
    int b = blockIdx.z;
    int yb = blockIdx.y, xb = blockIdx.x;
    int mBase = yb*128, nBase = xb*128;
    int wm = wid>>1, wn = wid&1;

    const unsigned char* Asrc = Abase + (size_t)b*sAb + (size_t)yb*63*16384;
    const unsigned char* Bsrc = Bbase + (size_t)b*sBb + (size_t)xb*63*16384;

    if (tid==0){ mbar_init(mb,1); mbar_init(mb+8,1); mbar_init(mb+16,1); }
    __syncthreads();
    if (tid==0){
        #pragma unroll
        for (int p=0;p<NSTAGE;p++){
            uint32_t bar = mb + p*8;
            mbar_expect_tx(bar, 32768);
            tma_bulk_g2s(sb + p*S_STG,          Asrc + (size_t)p*16384, 16384, bar);
            tma_bulk_g2s(sb + p*S_STG + 16384,  Bsrc + (size_t)p*16384, 16384, bar);
        }
    }

    float acc[2][8][4];
    #pragma unroll
    for (int i=0;i<2;i++)
        #pragma unroll
        for (int j=0;j<8;j++)
            #pragma unroll
            for (int q=0;q<4;q++) acc[i][j][q]=0.f;

    for (int c=0;c<NCHUNK;c++){
        int s = c%NSTAGE;
        mbar_wait(mb + s*8, (uint32_t)((c/NSTAGE)&1));
        uint32_t stg = sb + s*S_STG;
        #pragma unroll
        for (int ks=0;ks<4;ks++){
            uint32_t ah[2][4];
            #pragma unroll
            for (int mt=0;mt<2;mt++){
                int row = wm*32 + mt*16 + (lane&15);
                uint32_t bo = SWZ(row*128 + ks*32 + (lane>>4)*16);
                ldsm4(ah[mt], stg + bo);
            }
            uint32_t bh[8][2];
            #pragma unroll
            for (int nt=0;nt<8;nt++){
                int row = wn*64 + nt*8 + (lane&7);
                uint32_t bo = SWZ(row*128 + ks*32 + ((lane>>3)&1)*16);
                ldsm2(bh[nt], stg + 16384 + bo);
            }
            #pragma unroll
            for (int mt=0;mt<2;mt++)
                #pragma unroll
                for (int nt=0;nt<8;nt++)
                    mma16816h(acc[mt][nt], ah[mt], bh[nt]);
        }
        __syncthreads();
        if (tid==0 && (c+NSTAGE) < NCHUNK){
            int cn = c+NSTAGE;
            uint32_t bar = mb + s*8;
            mbar_expect_tx(bar, 32768);
            tma_bulk_g2s(stg,          Asrc + (size_t)cn*16384, 16384, bar);
            tma_bulk_g2s(stg + 16384,  Bsrc + (size_t)cn*16384, 16384, bar);
        }
    }

    float* C = gC + (size_t)b*NN*256;
    const float* D = gD ? gD + (size_t)b*NN*256 : (const float*)0;
    int tig = lane&3, grp = lane>>2;
    #pragma unroll
    for (int mt=0;mt<2;mt++){
        int r0 = mBase + wm*32 + mt*16 + grp;
        int r1 = r0 + 8;
        #pragma unroll
        for (int nt=0;nt<8;nt++){
            int c0 = nBase + wn*64 + nt*8 + tig*2;
            if (r0 < NN){
                float v0 = alpha*acc[mt][nt][0];
                float v1 = alpha*acc[mt][nt][1];
                if (D){ v0 += beta*D[(size_t)r0*256 + c0]; v1 += beta*D[(size_t)r0*256 + c0 + 1]; }
                C[(size_t)r0*256 + c0]     = v0;
                C[(size_t)r0*256 + c0 + 1] = v1;
            }
            if (r1 < NN){
                float v2 = alpha*acc[mt][nt][2];
                float v3 = alpha*acc[mt][nt][3];
                if (D){ v2 += beta*D[(size_t)r1*256 + c0]; v3 += beta*D[(size_t)r1*256 + c0 + 1]; }
                C[(size_t)r1*256 + c0]     = v2;
                C[(size_t)r1*256 + c0 + 1] = v3;
            }
        }
    }
}

// softmax over last dim of S; writes fp16 probs into tiled A layout g_PT
__global__ void k_softmax(){
    __shared__ float row[NN];
    __shared__ float red[256];
    int tid = threadIdx.x;
    int b = blockIdx.x / NN;
    int n = blockIdx.x % NN;
    size_t base = (size_t)blockIdx.x * NN;
    float m = -1e30f;
    for (int i = tid; i < NN; i += 256){ float v = g_S[base+i]; row[i]=v; m = fmaxf(m,v); }
    red[tid]=m; __syncthreads();
    for (int o=128;o>0;o>>=1){ if (tid<o) red[tid]=fmaxf(red[tid],red[tid+o]); __syncthreads(); }
    m = red[0]; __syncthreads();
    float s = 0.f;
    for (int i = tid; i < NN; i += 256){ float e = __expf(row[i]-m); row[i]=e; s += e; }
    red[tid]=s; __syncthreads();
    for (int o=128;o>0;o>>=1){ if (tid<o) red[tid]+=red[tid+o]; __syncthreads(); }
    float inv = 1.f/red[0];
    int yb = n>>7, r = n&127;
    unsigned char* Pb = g_PT + (size_t)(b*32 + yb)*63*16384;
    for (int i = tid; i < NN; i += 256){
        __half h = __float2half_rn(row[i]*inv);
        size_t tb = (size_t)(i>>6)*16384;
        uint32_t off = SWZ((uint32_t)(r*128 + (i&63)*2));
        *(__half*)(Pb + tb + off) = h;
    }
}

__global__ void k_final(const float* __restrict__ x, const float* __restrict__ cheb,
                        const float* __restrict__ tw, const float* __restrict__ tb){
    int bn = blockIdx.x;
    int tid = threadIdx.x;
    __shared__ float xs[256], t0[256], t1[256], t2[256], ts0[16], ts1[16], ts2[16];
    size_t rb = (size_t)bn*256;
    xs[tid]=x[rb+tid]; t0[tid]=g_Tx0[rb+tid]; t1[tid]=g_Tx1[rb+tid]; t2[tid]=g_Tx2[rb+tid];
    __syncthreads();
    if (tid < 48){
        int kk = tid>>4, f = tid&15;
        const float* src = (kk==0) ? t0 : ((kk==1) ? t1 : t2);
        float s = 0.f;
        #pragma unroll
        for (int t=0;t<16;t++) s += src[f*16+t];
        float* dst = (kk==0) ? ts0 : ((kk==1) ? ts1 : ts2);
        dst[f] = s;
    }
    __syncthreads();
    if (tid < 16){
        int o = tid;
        float tm = 0.f;
        #pragma unroll
        for (int c=0;c<16;c++)
            #pragma unroll
            for (int t=0;t<16;t++) tm += xs[c*16+t]*tw[(o*16+c)*16+t];
        float sp = 0.f;
        #pragma unroll
        for (int f=0;f<16;f++)
            sp += ts0[f]*cheb[f*16+o] + ts1[f]*cheb[256+f*16+o] + ts2[f]*cheb[512+f*16+o];
        g_y[bn*16+o] = sp*(1.f/16.f) + tm + tb[o] + xs[o*16+15];
    }
}

__global__ void k_stats(){
    int b = blockIdx.x, tid = threadIdx.x;
    double s = 0.0, ss = 0.0;
    for (int i = tid; i < NN*OO; i += 256){
        float v = g_y[b*NN*OO + i];
        s += (double)v; ss += (double)v*(double)v;
    }
    __shared__ double rs[256], rq[256];
    rs[tid]=s; rq[tid]=ss; __syncthreads();
    for (int o=128;o>0;o>>=1){ if (tid<o){ rs[tid]+=rs[tid+o]; rq[tid]+=rq[tid+o]; } __syncthreads(); }
    if (tid==0){
        double mean = rs[0]/(double)(NN*OO);
        double var  = rq[0]/(double)(NN*OO) - mean*mean;
        g_stats[b*2]   = (float)mean;
        g_stats[b*2+1] = (float)(1.0/sqrt(var + 1e-5));
    }
}
__global__ void k_out(const float* __restrict__ lng, const float* __restrict__ lnb,
                      float* __restrict__ out){
    int i = blockIdx.x*256 + threadIdx.x;
    if (i < BB*NN*OO){
        int b  = i / (NN*OO);
        int no = i % (NN*OO);
        float v = (g_y[i]-g_stats[b*2])*g_stats[b*2+1]*lng[no] + lnb[no];
        out[i] = fmaxf(v, 0.f);
    }
}

extern "C" void kernel_launch(void* const* d_in, const int* in_sizes, int n_in,
                              void* d_out, int out_size){
    const float* x    = (const float*)d_in[0];
    const float* lap  = (const float*)d_in[1];
    const float* W1   = (const float*)d_in[2];
    const float* W2   = (const float*)d_in[3];
    const float* W3   = (const float*)d_in[4];
    const float* bs   = (const float*)d_in[5];
    const float* Vs   = (const float*)d_in[6];
    const float* U1   = (const float*)d_in[7];
    const float* U2   = (const float*)d_in[8];
    const float* U3   = (const float*)d_in[9];
    const float* be   = (const float*)d_in[10];
    const float* Ve   = (const float*)d_in[11];
    const float* cheb = (const float*)d_in[12];
    const float* tw   = (const float*)d_in[13];
    const float* tb   = (const float*)d_in[14];
    const float* lng  = (const float*)d_in[15];
    const float* lnb  = (const float*)d_in[16];
    float* out = (float*)d_out;

    static int smem_set = 0;
    if (!smem_set){
        cudaFuncSetAttribute(gemm_S_mma, cudaFuncAttributeMaxDynamicSharedMemorySize, SMEM_REQ_S);
        cudaFuncSetAttribute(gemm_sm,    cudaFuncAttributeMaxDynamicSharedMemorySize, SMEM_REQ_S);
        smem_set = 1;
    }

    float *g_T0p, *g_T1p, *g_T2p, *g_xTp;
    unsigned char *PT_p, *lapT_p, *bTt_p;
    cudaGetSymbolAddress((void**)&g_T0p, g_Tx0);
    cudaGetSymbolAddress((void**)&g_T1p, g_Tx1);
    cudaGetSymbolAddress((void**)&g_T2p, g_Tx2);
    cudaGetSymbolAddress((void**)&g_xTp, g_xTAt);
    cudaGetSymbolAddress((void**)&PT_p,   g_PT);
    cudaGetSymbolAddress((void**)&lapT_p, g_lapT);
    cudaGetSymbolAddress((void**)&bTt_p,  g_bTt);

    const long long sA_PT  = (long long)32*63*16384;
    const long long sB_bT  = (long long)2*63*16384;

    k_u2u3<<<(NN+255)/256, 256>>>(U2, U3);
    k_tred<<<BB*TT, 256>>>(x, U1);
    k_E<<<1, 256>>>(Ve, be);
    k_xTAt<<<BB*NN, 256>>>(x, W1, W2, W3);
    k_vs_tiled<<<(NN*NN+255)/256, 256>>>(Vs);
    k_lap_tiled<<<(NN*NN+255)/256, 256>>>(lap);
    k_zero_cs<<<(BB*NN+255)/256, 256>>>();
    k_sigP<<<dim3(125,125,BB), 256>>>(bs);

    // S = (Vs-.5)@(sig-.5) + 0.5*colsum   (single-pass fp16, bulk-TMA, occ 2)
    gemm_S_mma<<<dim3(32,32,BB), 256, SMEM_REQ_S>>>();

    k_softmax<<<BB*NN, 256>>>();                  // -> fp16 tiled g_PT
    k_tsplit<<<dim3(125,8,BB), 256>>>(g_xTp);     // xTAt^T -> g_bTt

    // Tx0 = softmax(S) @ xTAt
    gemm_sm<<<dim3(2,32,BB), 256, SMEM_REQ_S>>>(PT_p, sA_PT, bTt_p, sB_bT,
                                                g_T0p, (const float*)0, 1.f, 0.f);
    k_tsplit<<<dim3(125,8,BB), 256>>>(g_T0p);
    // Tx1 = lap @ Tx0
    gemm_sm<<<dim3(2,32,BB), 256, SMEM_REQ_S>>>(lapT_p, 0LL, bTt_p, sB_bT,
                                                g_T1p, (const float*)0, 1.f, 0.f);
    k_tsplit<<<dim3(125,8,BB), 256>>>(g_T1p);
    // Tx2 = 2*lap @ Tx1 - Tx0
    gemm_sm<<<dim3(2,32,BB), 256, SMEM_REQ_S>>>(lapT_p, 0LL, bTt_p, sB_bT,
                                                g_T2p, g_T0p, 2.f, -1.f);

    k_final<<<BB*NN, 256>>>(x, cheb, tw, tb);
    k_stats<<<BB, 256>>>();
    k_out<<<(BB*NN*OO+255)/256, 256>>>(lng, lnb, out);
}